// round 14
// baseline (speedup 1.0000x reference)
#include <cuda_runtime.h>
#include <math.h>
#include <float.h>

// ---------------- problem constants ----------------
#define G_      32
#define EPG     16384                 // edges per graph
#define EDGES   (G_ * EPG)
#define H_      128
#define NT_MAX  32768

static const int NCUR_H[4] = {1024, 820, 656, 525};
static const int KSEL_H[4] = {820, 656, 525, 420};

// gemm smem: meanT 128x68 (K-major) + W 2x16x128 + H 2x16x64  (floats)
#define SMEM_GEMM_BYTES ((128 * 68 + 2 * 16 * 128 + 2 * 16 * 64) * 4)
// mega smem (select only)
#define MEGA_SMEM (3 * 4096 + 4096)

// ---------------- device scratch (double-buffered pooled CSR) ----------------
__device__ __align__(16) float g_bufA[NT_MAX * H_];  // pooled h (input of next block)
__device__ __align__(16) float g_bufB[NT_MAX * H_];  // conv out (raw, pre-BN)
__device__ int   g_cnt0[NT_MAX],  g_cnt1[NT_MAX];
__device__ int   g_off0[NT_MAX],  g_off1[NT_MAX];
__device__ int   g_csrA[EDGES],   g_csrB[EDGES];
__device__ int   g_mapG[NT_MAX];
__device__ int   g_permG[NT_MAX];
__device__ float g_score[NT_MAX];
__device__ __align__(16) float g_colsum[4 * H_];
__device__ __align__(16) float g_colsq [4 * H_];
__device__ float g_flat[G_ * 1024];
__device__ unsigned int g_fmax[G_ * 4 * 128];

// ---------------- csr0 ----------------
__global__ __launch_bounds__(1024)
void csr0_kernel(const int* __restrict__ ei) {
    __shared__ int cnt[1024], off[1024], cur[1024];
    __shared__ int wsum[32];
    int g = blockIdx.x, tid = threadIdx.x;
    int lane = tid & 31, wid = tid >> 5;
    cnt[tid] = 0;
    __syncthreads();
    const int* srcp = ei + g * EPG;
    const int* dstp = ei + EDGES + g * EPG;
    for (int e = tid; e < EPG; e += 1024)
        atomicAdd(&cnt[dstp[e] - (g << 10)], 1);
    __syncthreads();
    int v = cnt[tid];
    int inc = v;
    #pragma unroll
    for (int o = 1; o < 32; o <<= 1) {
        int t = __shfl_up_sync(0xffffffffu, inc, o);
        if (lane >= o) inc += t;
    }
    if (lane == 31) wsum[wid] = inc;
    __syncthreads();
    if (wid == 0) {
        int ws = wsum[lane], wi = ws;
        #pragma unroll
        for (int o = 1; o < 32; o <<= 1) {
            int t = __shfl_up_sync(0xffffffffu, wi, o);
            if (lane >= o) wi += t;
        }
        wsum[lane] = wi - ws;
    }
    __syncthreads();
    int ex = wsum[wid] + inc - v;
    off[tid] = ex;
    g_off0[g * 1024 + tid] = g * EPG + ex;
    g_cnt0[g * 1024 + tid] = v;
    cur[tid] = 0;
    __syncthreads();
    for (int e = tid; e < EPG; e += 1024) {
        int s = srcp[e];
        int d = dstp[e] - (g << 10);
        int pos = atomicAdd(&cur[d], 1);
        g_csrA[g * EPG + off[d] + pos] = s;
    }
    int i = g * 1024 + tid;
    g_flat[i] = 0.f;
    if (i < G_ * 4 * 128) g_fmax[i] = 0u;
    if (g == 0 && tid < 4 * H_) { g_colsum[tid] = 0.f; g_colsq[tid] = 0.f; }
}

// ---------------- wide CSR compaction ----------------
__global__ __launch_bounds__(256)
void compact_kernel(int ncur, int ksel, int sel) {
    const int* ocnt = sel ? g_cnt1 : g_cnt0;
    const int* ooff = sel ? g_off1 : g_off0;
    const int* ocsr = sel ? g_csrB : g_csrA;
    int* ncnt = sel ? g_cnt0 : g_cnt1;
    int* noff = sel ? g_off0 : g_off1;
    int* ncsr = sel ? g_csrA : g_csrB;

    int n = (blockIdx.x * blockDim.x + threadIdx.x) >> 5;
    int lane = threadIdx.x & 31;
    if (n >= G_ * ksel) return;
    int g = n / ksel;
    int og = g * ncur + g_permG[n];
    int deg  = ocnt[og];
    int base = ooff[og];
    int gk = g * ksel;
    int cum = 0;
    for (int j0 = 0; j0 < deg; j0 += 32) {
        int j = j0 + lane;
        int m = -1;
        if (j < deg) m = g_mapG[ocsr[base + j]];
        unsigned int mk = __ballot_sync(0xffffffffu, m >= 0);
        if (m >= 0) {
            int pos = __popc(mk & ((1u << lane) - 1u));
            ncsr[base + cum + pos] = gk + m;
        }
        cum += __popc(mk);
    }
    if (lane == 0) { ncnt[n] = cum; noff[n] = base; }
}

// ---------------- fused gather-mean + GEMM + BN-stats (64-row tile, K-major mean) ----------------
__global__ __launch_bounds__(256, 3)
void gemm_kernel(const float* __restrict__ x, int first, int slot, int sel,
                 const float* __restrict__ Wl, const float* __restrict__ Wr,
                 const float* __restrict__ bb, int nt) {
    extern __shared__ float smem[];
    float* meanT = smem;                        // [128][68] K-major: meanT[k*68 + row]
    float* WshB  = smem + 128 * 68;             // [2][16][128]
    float* HshB  = WshB + 2 * 16 * 128;         // [2][16][64]
    #define WSH(bf,k,c) WshB[(bf) * 2048 + (k) * 128 + (c)]
    #define HSH(bf,k,m) HshB[(bf) * 1024 + (k) * 64 + (m)]

    const int* cnti = sel ? g_cnt1 : g_cnt0;
    const int* offi = sel ? g_off1 : g_off0;
    const int* csri = sel ? g_csrB : g_csrA;

    const float* hin = first ? x : g_bufA;
    int row0 = blockIdx.x * 64;
    int tid = threadIdx.x;
    int w = tid >> 5, lane = tid & 31;
    int tx = tid & 15, ty = tid >> 4;
    int rm = ty * 4, cn = tx * 4;

    float4 pw[2];
    #pragma unroll
    for (int i = 0; i < 2; i++) {
        int idx = tid * 2 + i;
        int kk = idx >> 5, c = (idx & 31) * 4;
        pw[i] = *(const float4*)(Wl + (size_t)kk * H_ + c);
    }

    // ---- phase 1: gather means, store K-major ----
    for (int i = 0; i < 8; i++) {
        int rl = w * 8 + i;
        int row = row0 + rl;
        float4 acc = make_float4(0.f, 0.f, 0.f, 0.f);
        if (row < nt) {
            int deg  = cnti[row];
            int base = offi[row];
            int j = 0;
            for (; j + 8 <= deg; j += 8) {
                int s0 = csri[base + j + 0];
                int s1 = csri[base + j + 1];
                int s2 = csri[base + j + 2];
                int s3 = csri[base + j + 3];
                int s4 = csri[base + j + 4];
                int s5 = csri[base + j + 5];
                int s6 = csri[base + j + 6];
                int s7 = csri[base + j + 7];
                float4 v0 = *((const float4*)(hin + (size_t)s0 * H_) + lane);
                float4 v1 = *((const float4*)(hin + (size_t)s1 * H_) + lane);
                float4 v2 = *((const float4*)(hin + (size_t)s2 * H_) + lane);
                float4 v3 = *((const float4*)(hin + (size_t)s3 * H_) + lane);
                float4 v4 = *((const float4*)(hin + (size_t)s4 * H_) + lane);
                float4 v5 = *((const float4*)(hin + (size_t)s5 * H_) + lane);
                float4 v6 = *((const float4*)(hin + (size_t)s6 * H_) + lane);
                float4 v7 = *((const float4*)(hin + (size_t)s7 * H_) + lane);
                acc.x += ((v0.x + v1.x) + (v2.x + v3.x)) + ((v4.x + v5.x) + (v6.x + v7.x));
                acc.y += ((v0.y + v1.y) + (v2.y + v3.y)) + ((v4.y + v5.y) + (v6.y + v7.y));
                acc.z += ((v0.z + v1.z) + (v2.z + v3.z)) + ((v4.z + v5.z) + (v6.z + v7.z));
                acc.w += ((v0.w + v1.w) + (v2.w + v3.w)) + ((v4.w + v5.w) + (v6.w + v7.w));
            }
            for (; j < deg; j++) {
                int s0 = csri[base + j];
                float4 a = *((const float4*)(hin + (size_t)s0 * H_) + lane);
                acc.x += a.x; acc.y += a.y; acc.z += a.z; acc.w += a.w;
            }
            float inv = 1.0f / fmaxf((float)deg, 1.0f);
            acc.x *= inv; acc.y *= inv; acc.z *= inv; acc.w *= inv;
        }
        int kc = lane * 4;
        meanT[(kc + 0) * 68 + rl] = acc.x;
        meanT[(kc + 1) * 68 + rl] = acc.y;
        meanT[(kc + 2) * 68 + rl] = acc.z;
        meanT[(kc + 3) * 68 + rl] = acc.w;
    }
    #pragma unroll
    for (int i = 0; i < 2; i++) {
        int idx = tid * 2 + i;
        int kk = idx >> 5, c = (idx & 31) * 4;
        *(float4*)&WSH(0, kk, c) = pw[i];
    }
    __syncthreads();

    float acc[4][8];
    #pragma unroll
    for (int i = 0; i < 4; i++)
        #pragma unroll
        for (int j = 0; j < 8; j++) acc[i][j] = 0.f;

    int cur = 0;
    float4 ph;

    // ---- first half: k = 0..127, A from meanT (LDS.128) ----
    for (int kbi = 0; kbi < 8; kbi++) {
        int kwb = (kbi + 1) * 16;
        #pragma unroll
        for (int i = 0; i < 2; i++) {
            int idx = tid * 2 + i;
            int kk = idx >> 5, c = (idx & 31) * 4;
            int kw = kwb + kk;
            const float* ws = (kw < 128) ? (Wl + (size_t)kw * H_ + c)
                                         : (Wr + (size_t)(kw - 128) * H_ + c);
            pw[i] = *(const float4*)ws;
        }
        if (kbi == 7) {
            int r = tid >> 2, kc = (tid & 3) * 4;
            int row = row0 + r;
            ph = (row < nt) ? *(const float4*)(hin + (size_t)row * H_ + kc)
                            : make_float4(0.f, 0.f, 0.f, 0.f);
        }
        int kb = kbi * 16;
        #pragma unroll
        for (int kk = 0; kk < 16; kk++) {
            int kcol = kb + kk;
            float4 a0 = *(const float4*)&meanT[kcol * 68 + rm];
            float4 b0 = *(const float4*)&WSH(cur, kk, cn);
            float4 b1 = *(const float4*)&WSH(cur, kk, cn + 64);
            float a[4] = {a0.x, a0.y, a0.z, a0.w};
            float bv[8] = {b0.x, b0.y, b0.z, b0.w, b1.x, b1.y, b1.z, b1.w};
            #pragma unroll
            for (int i = 0; i < 4; i++)
                #pragma unroll
                for (int j = 0; j < 8; j++)
                    acc[i][j] += a[i] * bv[j];
        }
        #pragma unroll
        for (int i = 0; i < 2; i++) {
            int idx = tid * 2 + i;
            int kk = idx >> 5, c = (idx & 31) * 4;
            *(float4*)&WSH(cur ^ 1, kk, c) = pw[i];
        }
        if (kbi == 7) {
            int r = tid >> 2, kc = (tid & 3) * 4;
            HSH(cur ^ 1, kc + 0, r) = ph.x;
            HSH(cur ^ 1, kc + 1, r) = ph.y;
            HSH(cur ^ 1, kc + 2, r) = ph.z;
            HSH(cur ^ 1, kc + 3, r) = ph.w;
        }
        __syncthreads();
        cur ^= 1;
    }

    // ---- second half: k = 128..255, A from Hsh ----
    for (int kbi = 8; kbi < 16; kbi++) {
        if (kbi < 15) {
            int kwb = (kbi + 1) * 16;
            int hb  = (kbi + 1 - 8) * 16;
            #pragma unroll
            for (int i = 0; i < 2; i++) {
                int idx = tid * 2 + i;
                int kk = idx >> 5, c = (idx & 31) * 4;
                pw[i] = *(const float4*)(Wr + (size_t)(kwb + kk - 128) * H_ + c);
            }
            int r = tid >> 2, kc = (tid & 3) * 4;
            int row = row0 + r;
            ph = (row < nt) ? *(const float4*)(hin + (size_t)row * H_ + hb + kc)
                            : make_float4(0.f, 0.f, 0.f, 0.f);
        }
        #pragma unroll
        for (int kk = 0; kk < 16; kk++) {
            float4 a0 = *(const float4*)&HSH(cur, kk, rm);
            float4 b0 = *(const float4*)&WSH(cur, kk, cn);
            float4 b1 = *(const float4*)&WSH(cur, kk, cn + 64);
            float a[4] = {a0.x, a0.y, a0.z, a0.w};
            float bv[8] = {b0.x, b0.y, b0.z, b0.w, b1.x, b1.y, b1.z, b1.w};
            #pragma unroll
            for (int i = 0; i < 4; i++)
                #pragma unroll
                for (int j = 0; j < 8; j++)
                    acc[i][j] += a[i] * bv[j];
        }
        if (kbi < 15) {
            #pragma unroll
            for (int i = 0; i < 2; i++) {
                int idx = tid * 2 + i;
                int kk = idx >> 5, c = (idx & 31) * 4;
                *(float4*)&WSH(cur ^ 1, kk, c) = pw[i];
            }
            int r = tid >> 2, kc = (tid & 3) * 4;
            HSH(cur ^ 1, kc + 0, r) = ph.x;
            HSH(cur ^ 1, kc + 1, r) = ph.y;
            HSH(cur ^ 1, kc + 2, r) = ph.z;
            HSH(cur ^ 1, kc + 3, r) = ph.w;
        }
        __syncthreads();
        cur ^= 1;
    }

    // ---- epilogue ----
    float4 bia0 = *(const float4*)&bb[cn];
    float4 bia1 = *(const float4*)&bb[cn + 64];
    float bias[8] = {bia0.x, bia0.y, bia0.z, bia0.w, bia1.x, bia1.y, bia1.z, bia1.w};
    float psum[8], psq[8];
    #pragma unroll
    for (int j = 0; j < 8; j++) { psum[j] = 0.f; psq[j] = 0.f; }
    #pragma unroll
    for (int i = 0; i < 4; i++) {
        int row = row0 + rm + i;
        if (row < nt) {
            float v[8];
            #pragma unroll
            for (int j = 0; j < 8; j++) {
                v[j] = acc[i][j] + bias[j];
                psum[j] += v[j];
                psq[j]  += v[j] * v[j];
            }
            *(float4*)(g_bufB + (size_t)row * H_ + cn)      = make_float4(v[0], v[1], v[2], v[3]);
            *(float4*)(g_bufB + (size_t)row * H_ + cn + 64) = make_float4(v[4], v[5], v[6], v[7]);
        }
    }
    __syncthreads();
    float* sumS = smem;           // [16][128]
    float* sqS  = smem + 2048;    // [16][128]
    #pragma unroll
    for (int j = 0; j < 4; j++) {
        sumS[ty * 128 + cn + j]      = psum[j];
        sumS[ty * 128 + cn + 64 + j] = psum[4 + j];
        sqS [ty * 128 + cn + j]      = psq[j];
        sqS [ty * 128 + cn + 64 + j] = psq[4 + j];
    }
    __syncthreads();
    if (tid < 128) {
        float s = 0.f, q = 0.f;
        #pragma unroll
        for (int t = 0; t < 16; t++) {
            s += sumS[t * 128 + tid];
            q += sqS [t * 128 + tid];
        }
        atomicAdd(&g_colsum[slot * H_ + tid], s);
        atomicAdd(&g_colsq [slot * H_ + tid], q);
    }
    #undef WSH
    #undef HSH
}

// ---------------- wide score-only BN kernel (no writeback) ----------------
__global__ __launch_bounds__(256)
void bnscore_kernel(const float* __restrict__ gw, const float* __restrict__ be,
                    const float* __restrict__ p, int nt, float invnt, int slot) {
    int row = blockIdx.x * 8 + (threadIdx.x >> 5);
    int lane = threadIdx.x & 31;
    if (row >= nt) return;
    int c = lane * 4;
    float4 h  = *(const float4*)(g_bufB + (size_t)row * H_ + c);
    float4 cs = *(const float4*)&g_colsum[slot * H_ + c];
    float4 cq = *(const float4*)&g_colsq [slot * H_ + c];
    float4 gv = *(const float4*)&gw[c];
    float4 bv = *(const float4*)&be[c];
    float4 pv = *(const float4*)&p[c];
    float hh[4]  = {h.x, h.y, h.z, h.w};
    float css[4] = {cs.x, cs.y, cs.z, cs.w};
    float cqq[4] = {cq.x, cq.y, cq.z, cq.w};
    float gg[4]  = {gv.x, gv.y, gv.z, gv.w};
    float bbv[4] = {bv.x, bv.y, bv.z, bv.w};
    float pp[4]  = {pv.x, pv.y, pv.z, pv.w};
    float dot = 0.f, pn = 0.f;
    #pragma unroll
    for (int j = 0; j < 4; j++) {
        float mu = css[j] * invnt;
        float var = cqq[j] * invnt - mu * mu;
        float r = rsqrtf(var + 1e-5f);
        float v = (hh[j] - mu) * r * gg[j] + bbv[j];
        v = fmaxf(v, 0.f);
        dot += v * pp[j];
        pn  += pp[j] * pp[j];
    }
    #pragma unroll
    for (int o = 16; o > 0; o >>= 1) {
        dot += __shfl_down_sync(0xffffffffu, dot, o);
        pn  += __shfl_down_sync(0xffffffffu, pn, o);
    }
    if (lane == 0) g_score[row] = dot * rsqrtf(pn);
}

// ---------------- mega: radix-select -> publish map/perm ----------------
__global__ __launch_bounds__(1024)
void mega_kernel(int b, int ncur, int ksel) {
    extern __shared__ char smx[];
    int*   s_perm  = (int*)(smx);
    int*   s_map   = (int*)(smx + 4096);
    int*   s_red   = (int*)(smx + 8192);

    int g = blockIdx.x, tid = threadIdx.x;
    int lane = tid & 31, wid = tid >> 5;

    float myscore = (tid < ncur) ? g_score[g * ncur + tid] : -FLT_MAX;
    unsigned int key = 0u;
    if (tid < ncur) {
        unsigned int u = __float_as_uint(myscore);
        key = (u & 0x80000000u) ? ~u : (u | 0x80000000u);
    }

    int* hist  = s_red;
    int* hist2 = hist + 256;
    int* wtot  = hist + 512;
    int* s_sel = hist + 544;
    unsigned int prefixK = 0u, pmask = 0u;
    int remaining = ksel;
    #pragma unroll
    for (int pass = 0; pass < 4; pass++) {
        int shift = 24 - pass * 8;
        if (tid < 256) hist[tid] = 0;
        __syncthreads();
        if ((key & pmask) == prefixK)
            atomicAdd(&hist[(key >> shift) & 255u], 1);
        __syncthreads();
        int inc = 0;
        if (tid < 256) {
            inc = hist[255 - tid];
            #pragma unroll
            for (int o = 1; o < 32; o <<= 1) {
                int t = __shfl_up_sync(0xffffffffu, inc, o);
                if (lane >= o) inc += t;
            }
            if (lane == 31) wtot[tid >> 5] = inc;
        }
        __syncthreads();
        if (tid < 256) {
            int w8 = tid >> 5, add = 0;
            for (int q = 0; q < w8; q++) add += wtot[q];
            hist2[tid] = inc + add;
        }
        __syncthreads();
        if (tid < 256) {
            int sfx = hist2[tid];
            int above = (tid == 0) ? 0 : hist2[tid - 1];
            if (sfx >= remaining && above < remaining) {
                s_sel[0] = 255 - tid;
                s_sel[1] = above;
            }
        }
        __syncthreads();
        prefixK |= ((unsigned int)s_sel[0]) << shift;
        pmask   |= 255u << shift;
        remaining -= s_sel[1];
        __syncthreads();
    }
    unsigned int T = prefixK;
    int R = remaining;

    int strict = (key > T) ? 1 : 0;
    int tie    = (key == T) ? 1 : 0;
    int pk = strict | (tie << 16);
    int incs = pk;
    #pragma unroll
    for (int o = 1; o < 32; o <<= 1) {
        int t = __shfl_up_sync(0xffffffffu, incs, o);
        if (lane >= o) incs += t;
    }
    int* wsum = hist;
    if (lane == 31) wsum[wid] = incs;
    __syncthreads();
    if (wid == 0) {
        int ws = wsum[lane], wi = ws;
        #pragma unroll
        for (int o = 1; o < 32; o <<= 1) {
            int t = __shfl_up_sync(0xffffffffu, wi, o);
            if (lane >= o) wi += t;
        }
        wsum[lane] = wi - ws;
    }
    __syncthreads();
    int before = wsum[wid] + incs - pk;
    int sk_before  = before & 0xFFFF;
    int tie_before = before >> 16;
    int acc_f = strict | (tie & (tie_before < R ? 1 : 0));
    int newid = sk_before + (tie_before < R ? tie_before : R);
    s_map[tid] = acc_f ? newid : -1;
    if (acc_f) s_perm[newid] = tid;
    __syncthreads();

    if (tid < ncur && b < 3) g_mapG[g * ncur + tid] = s_map[tid];
    if (tid < ksel) g_permG[g * ksel + tid] = s_perm[tid];
}

// ---------------- wide gather + BN + ReLU + tanh gate + readout partials ----------------
__global__ __launch_bounds__(256)
void gatherread_kernel(int b, int ncur, int ksel, float invnt,
                       const float* __restrict__ gw, const float* __restrict__ be) {
    __shared__ float ssum[8][128];
    __shared__ unsigned int smax[8][128];
    int g = blockIdx.x;
    int row0 = blockIdx.y * 32;
    int tid = threadIdx.x, wid = tid >> 5, lane = tid & 31;
    int c = lane * 4;

    // per-thread BN constants for its 4 columns
    float4 cs = *(const float4*)&g_colsum[b * H_ + c];
    float4 cq = *(const float4*)&g_colsq [b * H_ + c];
    float4 gv = *(const float4*)&gw[c];
    float4 bv = *(const float4*)&be[c];
    float mu[4], rs[4];
    {
        float css[4] = {cs.x, cs.y, cs.z, cs.w};
        float cqq[4] = {cq.x, cq.y, cq.z, cq.w};
        #pragma unroll
        for (int j = 0; j < 4; j++) {
            mu[j] = css[j] * invnt;
            float var = cqq[j] * invnt - mu[j] * mu[j];
            rs[j] = rsqrtf(var + 1e-5f);
        }
    }
    float gg[4]  = {gv.x, gv.y, gv.z, gv.w};
    float bbv[4] = {bv.x, bv.y, bv.z, bv.w};

    float4 rsum = make_float4(0.f, 0.f, 0.f, 0.f);
    float4 rmax = make_float4(-FLT_MAX, -FLT_MAX, -FLT_MAX, -FLT_MAX);
    #pragma unroll
    for (int r = 0; r < 4; r++) {
        int nw = row0 + wid * 4 + r;
        if (nw < ksel) {
            int old = g_permG[g * ksel + nw];
            float t = tanhf(g_score[g * ncur + old]);
            float4 h = *((const float4*)(g_bufB + (size_t)(g * ncur + old) * H_) + lane);
            float hv[4] = {h.x, h.y, h.z, h.w};
            float o[4];
            #pragma unroll
            for (int j = 0; j < 4; j++) {
                float v = (hv[j] - mu[j]) * rs[j] * gg[j] + bbv[j];
                v = fmaxf(v, 0.f);
                o[j] = v * t;
            }
            float4 hh = make_float4(o[0], o[1], o[2], o[3]);
            if (b < 3) *((float4*)(g_bufA + (size_t)(g * ksel + nw) * H_) + lane) = hh;
            rsum.x += hh.x; rsum.y += hh.y; rsum.z += hh.z; rsum.w += hh.w;
            rmax.x = fmaxf(rmax.x, hh.x); rmax.y = fmaxf(rmax.y, hh.y);
            rmax.z = fmaxf(rmax.z, hh.z); rmax.w = fmaxf(rmax.w, hh.w);
        }
    }
    *(float4*)&ssum[wid][c] = rsum;
    {
        unsigned int ux = __float_as_uint(rmax.x);
        unsigned int uy = __float_as_uint(rmax.y);
        unsigned int uz = __float_as_uint(rmax.z);
        unsigned int uw = __float_as_uint(rmax.w);
        smax[wid][c + 0] = (ux & 0x80000000u) ? ~ux : (ux | 0x80000000u);
        smax[wid][c + 1] = (uy & 0x80000000u) ? ~uy : (uy | 0x80000000u);
        smax[wid][c + 2] = (uz & 0x80000000u) ? ~uz : (uz | 0x80000000u);
        smax[wid][c + 3] = (uw & 0x80000000u) ? ~uw : (uw | 0x80000000u);
    }
    __syncthreads();
    if (tid < 128) {
        float s = 0.f;
        unsigned int m = 0u;
        #pragma unroll
        for (int w = 0; w < 8; w++) {
            s += ssum[w][tid];
            m = max(m, smax[w][tid]);
        }
        atomicAdd(&g_flat[g * 1024 + b * 256 + tid], s);
        atomicMax(&g_fmax[(g * 4 + b) * 128 + tid], m);
    }
}

// ---------------- MLP head ----------------
__global__ __launch_bounds__(512)
void head_kernel(const float* __restrict__ Wd1, const float* __restrict__ bd1,
                 const float* __restrict__ Wd2, const float* __restrict__ bd2,
                 float* __restrict__ out) {
    __shared__ float a[1024];
    __shared__ float hd[512];
    int g = blockIdx.x, tid = threadIdx.x;
    for (int j = tid; j < 1024; j += 512) {
        int bb = j >> 8, r = j & 255;
        float v;
        if (r < 128) {
            v = g_flat[g * 1024 + bb * 256 + r];
        } else {
            unsigned int u = g_fmax[(g * 4 + bb) * 128 + (r - 128)];
            v = (u & 0x80000000u) ? __uint_as_float(u ^ 0x80000000u)
                                  : __uint_as_float(~u);
        }
        a[j] = v;
    }
    __syncthreads();
    {
        float a0 = 0.f, a1 = 0.f, a2 = 0.f, a3 = 0.f;
        #pragma unroll 4
        for (int kk = 0; kk < 1024; kk += 4) {
            a0 += a[kk + 0] * Wd1[(kk + 0) * 512 + tid];
            a1 += a[kk + 1] * Wd1[(kk + 1) * 512 + tid];
            a2 += a[kk + 2] * Wd1[(kk + 2) * 512 + tid];
            a3 += a[kk + 3] * Wd1[(kk + 3) * 512 + tid];
        }
        hd[tid] = fmaxf(a0 + a1 + a2 + a3 + bd1[tid], 0.f);
    }
    __syncthreads();
    if (tid < 320) {
        int cc = tid >> 5, l = tid & 31;
        float acc = 0.f;
        for (int kk = l; kk < 512; kk += 32) acc += hd[kk] * Wd2[kk * 10 + cc];
        #pragma unroll
        for (int o = 16; o > 0; o >>= 1) acc += __shfl_down_sync(0xffffffffu, acc, o);
        if (l == 0) out[g * 10 + cc] = acc + bd2[cc];
    }
}

// ---------------- launcher ----------------
extern "C" void kernel_launch(void* const* d_in, const int* in_sizes, int n_in,
                              void* d_out, int out_size) {
    const float* x  = (const float*)d_in[0];
    const int*   ei = (const int*)d_in[1];
    const float *Wl[4], *Wr[4], *bb[4], *gw[4], *be[4], *pp[4];
    int idx = 3;
    for (int b = 0; b < 4; b++) {
        Wl[b] = (const float*)d_in[idx++];
        Wr[b] = (const float*)d_in[idx++];
        bb[b] = (const float*)d_in[idx++];
        gw[b] = (const float*)d_in[idx++];
        be[b] = (const float*)d_in[idx++];
        pp[b] = (const float*)d_in[idx++];
    }
    const float* Wd1 = (const float*)d_in[27];
    const float* bd1 = (const float*)d_in[28];
    const float* Wd2 = (const float*)d_in[29];
    const float* bd2 = (const float*)d_in[30];
    float* out = (float*)d_out;

    cudaFuncSetAttribute(gemm_kernel, cudaFuncAttributeMaxDynamicSharedMemorySize,
                         SMEM_GEMM_BYTES);
    cudaFuncSetAttribute(mega_kernel, cudaFuncAttributeMaxDynamicSharedMemorySize,
                         MEGA_SMEM);

    csr0_kernel<<<G_, 1024>>>(ei);

    for (int b = 0; b < 4; b++) {
        int ncur = NCUR_H[b];
        int k    = KSEL_H[b];
        int nt   = G_ * ncur;
        int first = (b == 0) ? 1 : 0;
        int sel   = b & 1;
        float invnt = 1.0f / (float)nt;

        gemm_kernel<<<(nt + 63) / 64, 256, SMEM_GEMM_BYTES>>>(
            x, first, b, sel, Wl[b], Wr[b], bb[b], nt);
        bnscore_kernel<<<(nt + 7) / 8, 256>>>(gw[b], be[b], pp[b], nt, invnt, b);
        mega_kernel<<<G_, 1024, MEGA_SMEM>>>(b, ncur, k);
        gatherread_kernel<<<dim3(G_, (k + 31) / 32), 256>>>(b, ncur, k, invnt, gw[b], be[b]);
        if (b < 3)
            compact_kernel<<<(G_ * k * 32 + 255) / 256, 256>>>(ncur, k, sel);
    }
    head_kernel<<<G_, 512>>>(Wd1, bd1, Wd2, bd2, out);
}

// round 15
// speedup vs baseline: 1.0262x; 1.0262x over previous
#include <cuda_runtime.h>
#include <math.h>
#include <float.h>

// ---------------- problem constants ----------------
#define G_      32
#define EPG     16384                 // edges per graph
#define EDGES   (G_ * EPG)
#define H_      128
#define NT_MAX  32768

static const int NCUR_H[4] = {1024, 820, 656, 525};
static const int KSEL_H[4] = {820, 656, 525, 420};

// gemm smem: meanS 64x132 (row-major) + W 2x16x128 + H 2x16x64  (floats)
#define SMEM_GEMM_BYTES ((64 * 132 + 2 * 16 * 128 + 2 * 16 * 64) * 4)
// mega smem (select only)
#define MEGA_SMEM (3 * 4096 + 4096)

// ---------------- device scratch (double-buffered pooled CSR) ----------------
__device__ __align__(16) float g_bufA[NT_MAX * H_];  // pooled h (input of next block)
__device__ __align__(16) float g_bufB[NT_MAX * H_];  // conv out (raw, pre-BN)
__device__ int   g_cnt0[NT_MAX],  g_cnt1[NT_MAX];
__device__ int   g_off0[NT_MAX],  g_off1[NT_MAX];
__device__ int   g_csrA[EDGES],   g_csrB[EDGES];
__device__ int   g_mapG[NT_MAX];
__device__ int   g_permG[NT_MAX];
__device__ float g_score[NT_MAX];
__device__ __align__(16) float g_colsum[4 * H_];
__device__ __align__(16) float g_colsq [4 * H_];
__device__ float g_flat[G_ * 1024];
__device__ unsigned int g_fmax[G_ * 4 * 128];

// ---------------- csr0 ----------------
__global__ __launch_bounds__(1024)
void csr0_kernel(const int* __restrict__ ei) {
    __shared__ int cnt[1024], off[1024], cur[1024];
    __shared__ int wsum[32];
    int g = blockIdx.x, tid = threadIdx.x;
    int lane = tid & 31, wid = tid >> 5;
    cnt[tid] = 0;
    __syncthreads();
    const int* srcp = ei + g * EPG;
    const int* dstp = ei + EDGES + g * EPG;
    for (int e = tid; e < EPG; e += 1024)
        atomicAdd(&cnt[dstp[e] - (g << 10)], 1);
    __syncthreads();
    int v = cnt[tid];
    int inc = v;
    #pragma unroll
    for (int o = 1; o < 32; o <<= 1) {
        int t = __shfl_up_sync(0xffffffffu, inc, o);
        if (lane >= o) inc += t;
    }
    if (lane == 31) wsum[wid] = inc;
    __syncthreads();
    if (wid == 0) {
        int ws = wsum[lane], wi = ws;
        #pragma unroll
        for (int o = 1; o < 32; o <<= 1) {
            int t = __shfl_up_sync(0xffffffffu, wi, o);
            if (lane >= o) wi += t;
        }
        wsum[lane] = wi - ws;
    }
    __syncthreads();
    int ex = wsum[wid] + inc - v;
    off[tid] = ex;
    g_off0[g * 1024 + tid] = g * EPG + ex;
    g_cnt0[g * 1024 + tid] = v;
    cur[tid] = 0;
    __syncthreads();
    for (int e = tid; e < EPG; e += 1024) {
        int s = srcp[e];
        int d = dstp[e] - (g << 10);
        int pos = atomicAdd(&cur[d], 1);
        g_csrA[g * EPG + off[d] + pos] = s;
    }
    int i = g * 1024 + tid;
    g_flat[i] = 0.f;
    if (i < G_ * 4 * 128) g_fmax[i] = 0u;
    if (g == 0 && tid < 4 * H_) { g_colsum[tid] = 0.f; g_colsq[tid] = 0.f; }
}

// ---------------- wide CSR compaction ----------------
__global__ __launch_bounds__(256)
void compact_kernel(int ncur, int ksel, int sel) {
    const int* ocnt = sel ? g_cnt1 : g_cnt0;
    const int* ooff = sel ? g_off1 : g_off0;
    const int* ocsr = sel ? g_csrB : g_csrA;
    int* ncnt = sel ? g_cnt0 : g_cnt1;
    int* noff = sel ? g_off0 : g_off1;
    int* ncsr = sel ? g_csrA : g_csrB;

    int n = (blockIdx.x * blockDim.x + threadIdx.x) >> 5;
    int lane = threadIdx.x & 31;
    if (n >= G_ * ksel) return;
    int g = n / ksel;
    int og = g * ncur + g_permG[n];
    int deg  = ocnt[og];
    int base = ooff[og];
    int gk = g * ksel;
    int cum = 0;
    for (int j0 = 0; j0 < deg; j0 += 32) {
        int j = j0 + lane;
        int m = -1;
        if (j < deg) m = g_mapG[ocsr[base + j]];
        unsigned int mk = __ballot_sync(0xffffffffu, m >= 0);
        if (m >= 0) {
            int pos = __popc(mk & ((1u << lane) - 1u));
            ncsr[base + cum + pos] = gk + m;
        }
        cum += __popc(mk);
    }
    if (lane == 0) { ncnt[n] = cum; noff[n] = base; }
}

// ---------------- fused gather-mean + GEMM + BN-stats (64-row tile, row-major mean) ----------------
__global__ __launch_bounds__(256, 3)
void gemm_kernel(const float* __restrict__ x, int first, int slot, int sel,
                 const float* __restrict__ Wl, const float* __restrict__ Wr,
                 const float* __restrict__ bb, int nt) {
    extern __shared__ float smem[];
    float* meanS = smem;                        // [64][132]
    float* WshB  = smem + 64 * 132;             // [2][16][128]
    float* HshB  = WshB + 2 * 16 * 128;         // [2][16][64]
    #define WSH(bf,k,c) WshB[(bf) * 2048 + (k) * 128 + (c)]
    #define HSH(bf,k,m) HshB[(bf) * 1024 + (k) * 64 + (m)]

    const int* cnti = sel ? g_cnt1 : g_cnt0;
    const int* offi = sel ? g_off1 : g_off0;
    const int* csri = sel ? g_csrB : g_csrA;

    const float* hin = first ? x : g_bufA;
    int row0 = blockIdx.x * 64;
    int tid = threadIdx.x;
    int w = tid >> 5, lane = tid & 31;
    int tx = tid & 15, ty = tid >> 4;
    int rm = ty * 4, cn = tx * 4;

    float4 pw[2];
    #pragma unroll
    for (int i = 0; i < 2; i++) {
        int idx = tid * 2 + i;
        int kk = idx >> 5, c = (idx & 31) * 4;
        pw[i] = *(const float4*)(Wl + (size_t)kk * H_ + c);
    }

    // ---- phase 1: gather means (8 rows per warp, 8 loads in flight) ----
    for (int i = 0; i < 8; i++) {
        int rl = w * 8 + i;
        int row = row0 + rl;
        float4 acc = make_float4(0.f, 0.f, 0.f, 0.f);
        if (row < nt) {
            int deg  = cnti[row];
            int base = offi[row];
            int j = 0;
            for (; j + 8 <= deg; j += 8) {
                int s0 = csri[base + j + 0];
                int s1 = csri[base + j + 1];
                int s2 = csri[base + j + 2];
                int s3 = csri[base + j + 3];
                int s4 = csri[base + j + 4];
                int s5 = csri[base + j + 5];
                int s6 = csri[base + j + 6];
                int s7 = csri[base + j + 7];
                float4 v0 = *((const float4*)(hin + (size_t)s0 * H_) + lane);
                float4 v1 = *((const float4*)(hin + (size_t)s1 * H_) + lane);
                float4 v2 = *((const float4*)(hin + (size_t)s2 * H_) + lane);
                float4 v3 = *((const float4*)(hin + (size_t)s3 * H_) + lane);
                float4 v4 = *((const float4*)(hin + (size_t)s4 * H_) + lane);
                float4 v5 = *((const float4*)(hin + (size_t)s5 * H_) + lane);
                float4 v6 = *((const float4*)(hin + (size_t)s6 * H_) + lane);
                float4 v7 = *((const float4*)(hin + (size_t)s7 * H_) + lane);
                acc.x += ((v0.x + v1.x) + (v2.x + v3.x)) + ((v4.x + v5.x) + (v6.x + v7.x));
                acc.y += ((v0.y + v1.y) + (v2.y + v3.y)) + ((v4.y + v5.y) + (v6.y + v7.y));
                acc.z += ((v0.z + v1.z) + (v2.z + v3.z)) + ((v4.z + v5.z) + (v6.z + v7.z));
                acc.w += ((v0.w + v1.w) + (v2.w + v3.w)) + ((v4.w + v5.w) + (v6.w + v7.w));
            }
            for (; j < deg; j++) {
                int s0 = csri[base + j];
                float4 a = *((const float4*)(hin + (size_t)s0 * H_) + lane);
                acc.x += a.x; acc.y += a.y; acc.z += a.z; acc.w += a.w;
            }
            float inv = 1.0f / fmaxf((float)deg, 1.0f);
            acc.x *= inv; acc.y *= inv; acc.z *= inv; acc.w *= inv;
        }
        *(float4*)&meanS[rl * 132 + lane * 4] = acc;
    }
    #pragma unroll
    for (int i = 0; i < 2; i++) {
        int idx = tid * 2 + i;
        int kk = idx >> 5, c = (idx & 31) * 4;
        *(float4*)&WSH(0, kk, c) = pw[i];
    }
    __syncthreads();

    float acc[4][8];
    #pragma unroll
    for (int i = 0; i < 4; i++)
        #pragma unroll
        for (int j = 0; j < 8; j++) acc[i][j] = 0.f;

    int cur = 0;
    float4 ph;

    // ---- first half: k = 0..127, A from meanS (broadcast scalar LDS) ----
    for (int kbi = 0; kbi < 8; kbi++) {
        int kwb = (kbi + 1) * 16;
        #pragma unroll
        for (int i = 0; i < 2; i++) {
            int idx = tid * 2 + i;
            int kk = idx >> 5, c = (idx & 31) * 4;
            int kw = kwb + kk;
            const float* ws = (kw < 128) ? (Wl + (size_t)kw * H_ + c)
                                         : (Wr + (size_t)(kw - 128) * H_ + c);
            pw[i] = *(const float4*)ws;
        }
        if (kbi == 7) {
            int r = tid >> 2, kc = (tid & 3) * 4;
            int row = row0 + r;
            ph = (row < nt) ? *(const float4*)(hin + (size_t)row * H_ + kc)
                            : make_float4(0.f, 0.f, 0.f, 0.f);
        }
        int kb = kbi * 16;
        #pragma unroll
        for (int kk = 0; kk < 16; kk++) {
            int kcol = kb + kk;
            float a[4];
            #pragma unroll
            for (int i = 0; i < 4; i++) a[i] = meanS[(rm + i) * 132 + kcol];
            float4 b0 = *(const float4*)&WSH(cur, kk, cn);
            float4 b1 = *(const float4*)&WSH(cur, kk, cn + 64);
            float bv[8] = {b0.x, b0.y, b0.z, b0.w, b1.x, b1.y, b1.z, b1.w};
            #pragma unroll
            for (int i = 0; i < 4; i++)
                #pragma unroll
                for (int j = 0; j < 8; j++)
                    acc[i][j] += a[i] * bv[j];
        }
        #pragma unroll
        for (int i = 0; i < 2; i++) {
            int idx = tid * 2 + i;
            int kk = idx >> 5, c = (idx & 31) * 4;
            *(float4*)&WSH(cur ^ 1, kk, c) = pw[i];
        }
        if (kbi == 7) {
            int r = tid >> 2, kc = (tid & 3) * 4;
            HSH(cur ^ 1, kc + 0, r) = ph.x;
            HSH(cur ^ 1, kc + 1, r) = ph.y;
            HSH(cur ^ 1, kc + 2, r) = ph.z;
            HSH(cur ^ 1, kc + 3, r) = ph.w;
        }
        __syncthreads();
        cur ^= 1;
    }

    // ---- second half: k = 128..255, A from Hsh ----
    for (int kbi = 8; kbi < 16; kbi++) {
        if (kbi < 15) {
            int kwb = (kbi + 1) * 16;
            int hb  = (kbi + 1 - 8) * 16;
            #pragma unroll
            for (int i = 0; i < 2; i++) {
                int idx = tid * 2 + i;
                int kk = idx >> 5, c = (idx & 31) * 4;
                pw[i] = *(const float4*)(Wr + (size_t)(kwb + kk - 128) * H_ + c);
            }
            int r = tid >> 2, kc = (tid & 3) * 4;
            int row = row0 + r;
            ph = (row < nt) ? *(const float4*)(hin + (size_t)row * H_ + hb + kc)
                            : make_float4(0.f, 0.f, 0.f, 0.f);
        }
        #pragma unroll
        for (int kk = 0; kk < 16; kk++) {
            float4 a0 = *(const float4*)&HSH(cur, kk, rm);
            float4 b0 = *(const float4*)&WSH(cur, kk, cn);
            float4 b1 = *(const float4*)&WSH(cur, kk, cn + 64);
            float a[4] = {a0.x, a0.y, a0.z, a0.w};
            float bv[8] = {b0.x, b0.y, b0.z, b0.w, b1.x, b1.y, b1.z, b1.w};
            #pragma unroll
            for (int i = 0; i < 4; i++)
                #pragma unroll
                for (int j = 0; j < 8; j++)
                    acc[i][j] += a[i] * bv[j];
        }
        if (kbi < 15) {
            #pragma unroll
            for (int i = 0; i < 2; i++) {
                int idx = tid * 2 + i;
                int kk = idx >> 5, c = (idx & 31) * 4;
                *(float4*)&WSH(cur ^ 1, kk, c) = pw[i];
            }
            int r = tid >> 2, kc = (tid & 3) * 4;
            HSH(cur ^ 1, kc + 0, r) = ph.x;
            HSH(cur ^ 1, kc + 1, r) = ph.y;
            HSH(cur ^ 1, kc + 2, r) = ph.z;
            HSH(cur ^ 1, kc + 3, r) = ph.w;
        }
        __syncthreads();
        cur ^= 1;
    }

    // ---- epilogue ----
    float4 bia0 = *(const float4*)&bb[cn];
    float4 bia1 = *(const float4*)&bb[cn + 64];
    float bias[8] = {bia0.x, bia0.y, bia0.z, bia0.w, bia1.x, bia1.y, bia1.z, bia1.w};
    float psum[8], psq[8];
    #pragma unroll
    for (int j = 0; j < 8; j++) { psum[j] = 0.f; psq[j] = 0.f; }
    #pragma unroll
    for (int i = 0; i < 4; i++) {
        int row = row0 + rm + i;
        if (row < nt) {
            float v[8];
            #pragma unroll
            for (int j = 0; j < 8; j++) {
                v[j] = acc[i][j] + bias[j];
                psum[j] += v[j];
                psq[j]  += v[j] * v[j];
            }
            *(float4*)(g_bufB + (size_t)row * H_ + cn)      = make_float4(v[0], v[1], v[2], v[3]);
            *(float4*)(g_bufB + (size_t)row * H_ + cn + 64) = make_float4(v[4], v[5], v[6], v[7]);
        }
    }
    __syncthreads();
    float* sumS = smem;           // [16][128]
    float* sqS  = smem + 2048;    // [16][128]
    #pragma unroll
    for (int j = 0; j < 4; j++) {
        sumS[ty * 128 + cn + j]      = psum[j];
        sumS[ty * 128 + cn + 64 + j] = psum[4 + j];
        sqS [ty * 128 + cn + j]      = psq[j];
        sqS [ty * 128 + cn + 64 + j] = psq[4 + j];
    }
    __syncthreads();
    if (tid < 128) {
        float s = 0.f, q = 0.f;
        #pragma unroll
        for (int t = 0; t < 16; t++) {
            s += sumS[t * 128 + tid];
            q += sqS [t * 128 + tid];
        }
        atomicAdd(&g_colsum[slot * H_ + tid], s);
        atomicAdd(&g_colsq [slot * H_ + tid], q);
    }
    #undef WSH
    #undef HSH
}

// ---------------- wide score-only BN kernel (no writeback) ----------------
__global__ __launch_bounds__(256)
void bnscore_kernel(const float* __restrict__ gw, const float* __restrict__ be,
                    const float* __restrict__ p, int nt, float invnt, int slot) {
    int row = blockIdx.x * 8 + (threadIdx.x >> 5);
    int lane = threadIdx.x & 31;
    if (row >= nt) return;
    int c = lane * 4;
    float4 h  = *(const float4*)(g_bufB + (size_t)row * H_ + c);
    float4 cs = *(const float4*)&g_colsum[slot * H_ + c];
    float4 cq = *(const float4*)&g_colsq [slot * H_ + c];
    float4 gv = *(const float4*)&gw[c];
    float4 bv = *(const float4*)&be[c];
    float4 pv = *(const float4*)&p[c];
    float hh[4]  = {h.x, h.y, h.z, h.w};
    float css[4] = {cs.x, cs.y, cs.z, cs.w};
    float cqq[4] = {cq.x, cq.y, cq.z, cq.w};
    float gg[4]  = {gv.x, gv.y, gv.z, gv.w};
    float bbv[4] = {bv.x, bv.y, bv.z, bv.w};
    float pp[4]  = {pv.x, pv.y, pv.z, pv.w};
    float dot = 0.f, pn = 0.f;
    #pragma unroll
    for (int j = 0; j < 4; j++) {
        float mu = css[j] * invnt;
        float var = cqq[j] * invnt - mu * mu;
        float r = rsqrtf(var + 1e-5f);
        float v = (hh[j] - mu) * r * gg[j] + bbv[j];
        v = fmaxf(v, 0.f);
        dot += v * pp[j];
        pn  += pp[j] * pp[j];
    }
    #pragma unroll
    for (int o = 16; o > 0; o >>= 1) {
        dot += __shfl_down_sync(0xffffffffu, dot, o);
        pn  += __shfl_down_sync(0xffffffffu, pn, o);
    }
    if (lane == 0) g_score[row] = dot * rsqrtf(pn);
}

// ---------------- mega: radix-select -> publish map/perm ----------------
__global__ __launch_bounds__(1024)
void mega_kernel(int b, int ncur, int ksel) {
    extern __shared__ char smx[];
    int*   s_perm  = (int*)(smx);
    int*   s_map   = (int*)(smx + 4096);
    int*   s_red   = (int*)(smx + 8192);

    int g = blockIdx.x, tid = threadIdx.x;
    int lane = tid & 31, wid = tid >> 5;

    float myscore = (tid < ncur) ? g_score[g * ncur + tid] : -FLT_MAX;
    unsigned int key = 0u;
    if (tid < ncur) {
        unsigned int u = __float_as_uint(myscore);
        key = (u & 0x80000000u) ? ~u : (u | 0x80000000u);
    }

    int* hist  = s_red;
    int* hist2 = hist + 256;
    int* wtot  = hist + 512;
    int* s_sel = hist + 544;
    unsigned int prefixK = 0u, pmask = 0u;
    int remaining = ksel;
    #pragma unroll
    for (int pass = 0; pass < 4; pass++) {
        int shift = 24 - pass * 8;
        if (tid < 256) hist[tid] = 0;
        __syncthreads();
        if ((key & pmask) == prefixK)
            atomicAdd(&hist[(key >> shift) & 255u], 1);
        __syncthreads();
        int inc = 0;
        if (tid < 256) {
            inc = hist[255 - tid];
            #pragma unroll
            for (int o = 1; o < 32; o <<= 1) {
                int t = __shfl_up_sync(0xffffffffu, inc, o);
                if (lane >= o) inc += t;
            }
            if (lane == 31) wtot[tid >> 5] = inc;
        }
        __syncthreads();
        if (tid < 256) {
            int w8 = tid >> 5, add = 0;
            for (int q = 0; q < w8; q++) add += wtot[q];
            hist2[tid] = inc + add;
        }
        __syncthreads();
        if (tid < 256) {
            int sfx = hist2[tid];
            int above = (tid == 0) ? 0 : hist2[tid - 1];
            if (sfx >= remaining && above < remaining) {
                s_sel[0] = 255 - tid;
                s_sel[1] = above;
            }
        }
        __syncthreads();
        prefixK |= ((unsigned int)s_sel[0]) << shift;
        pmask   |= 255u << shift;
        remaining -= s_sel[1];
        __syncthreads();
    }
    unsigned int T = prefixK;
    int R = remaining;

    int strict = (key > T) ? 1 : 0;
    int tie    = (key == T) ? 1 : 0;
    int pk = strict | (tie << 16);
    int incs = pk;
    #pragma unroll
    for (int o = 1; o < 32; o <<= 1) {
        int t = __shfl_up_sync(0xffffffffu, incs, o);
        if (lane >= o) incs += t;
    }
    int* wsum = hist;
    if (lane == 31) wsum[wid] = incs;
    __syncthreads();
    if (wid == 0) {
        int ws = wsum[lane], wi = ws;
        #pragma unroll
        for (int o = 1; o < 32; o <<= 1) {
            int t = __shfl_up_sync(0xffffffffu, wi, o);
            if (lane >= o) wi += t;
        }
        wsum[lane] = wi - ws;
    }
    __syncthreads();
    int before = wsum[wid] + incs - pk;
    int sk_before  = before & 0xFFFF;
    int tie_before = before >> 16;
    int acc_f = strict | (tie & (tie_before < R ? 1 : 0));
    int newid = sk_before + (tie_before < R ? tie_before : R);
    s_map[tid] = acc_f ? newid : -1;
    if (acc_f) s_perm[newid] = tid;
    __syncthreads();

    if (tid < ncur && b < 3) g_mapG[g * ncur + tid] = s_map[tid];
    if (tid < ksel) g_permG[g * ksel + tid] = s_perm[tid];
}

// ---------------- wide gather + BN + ReLU + tanh gate + readout partials ----------------
__global__ __launch_bounds__(256)
void gatherread_kernel(int b, int ncur, int ksel, float invnt,
                       const float* __restrict__ gw, const float* __restrict__ be) {
    __shared__ float ssum[8][128];
    __shared__ unsigned int smax[8][128];
    int g = blockIdx.x;
    int row0 = blockIdx.y * 32;
    int tid = threadIdx.x, wid = tid >> 5, lane = tid & 31;
    int c = lane * 4;

    float4 cs = *(const float4*)&g_colsum[b * H_ + c];
    float4 cq = *(const float4*)&g_colsq [b * H_ + c];
    float4 gv = *(const float4*)&gw[c];
    float4 bv = *(const float4*)&be[c];
    float mu[4], rs[4];
    {
        float css[4] = {cs.x, cs.y, cs.z, cs.w};
        float cqq[4] = {cq.x, cq.y, cq.z, cq.w};
        #pragma unroll
        for (int j = 0; j < 4; j++) {
            mu[j] = css[j] * invnt;
            float var = cqq[j] * invnt - mu[j] * mu[j];
            rs[j] = rsqrtf(var + 1e-5f);
        }
    }
    float gg[4]  = {gv.x, gv.y, gv.z, gv.w};
    float bbv[4] = {bv.x, bv.y, bv.z, bv.w};

    float4 rsum = make_float4(0.f, 0.f, 0.f, 0.f);
    float4 rmax = make_float4(-FLT_MAX, -FLT_MAX, -FLT_MAX, -FLT_MAX);
    #pragma unroll
    for (int r = 0; r < 4; r++) {
        int nw = row0 + wid * 4 + r;
        if (nw < ksel) {
            int old = g_permG[g * ksel + nw];
            float t = tanhf(g_score[g * ncur + old]);
            float4 h = *((const float4*)(g_bufB + (size_t)(g * ncur + old) * H_) + lane);
            float hv[4] = {h.x, h.y, h.z, h.w};
            float o[4];
            #pragma unroll
            for (int j = 0; j < 4; j++) {
                float v = (hv[j] - mu[j]) * rs[j] * gg[j] + bbv[j];
                v = fmaxf(v, 0.f);
                o[j] = v * t;
            }
            float4 hh = make_float4(o[0], o[1], o[2], o[3]);
            if (b < 3) *((float4*)(g_bufA + (size_t)(g * ksel + nw) * H_) + lane) = hh;
            rsum.x += hh.x; rsum.y += hh.y; rsum.z += hh.z; rsum.w += hh.w;
            rmax.x = fmaxf(rmax.x, hh.x); rmax.y = fmaxf(rmax.y, hh.y);
            rmax.z = fmaxf(rmax.z, hh.z); rmax.w = fmaxf(rmax.w, hh.w);
        }
    }
    *(float4*)&ssum[wid][c] = rsum;
    {
        unsigned int ux = __float_as_uint(rmax.x);
        unsigned int uy = __float_as_uint(rmax.y);
        unsigned int uz = __float_as_uint(rmax.z);
        unsigned int uw = __float_as_uint(rmax.w);
        smax[wid][c + 0] = (ux & 0x80000000u) ? ~ux : (ux | 0x80000000u);
        smax[wid][c + 1] = (uy & 0x80000000u) ? ~uy : (uy | 0x80000000u);
        smax[wid][c + 2] = (uz & 0x80000000u) ? ~uz : (uz | 0x80000000u);
        smax[wid][c + 3] = (uw & 0x80000000u) ? ~uw : (uw | 0x80000000u);
    }
    __syncthreads();
    if (tid < 128) {
        float s = 0.f;
        unsigned int m = 0u;
        #pragma unroll
        for (int w = 0; w < 8; w++) {
            s += ssum[w][tid];
            m = max(m, smax[w][tid]);
        }
        atomicAdd(&g_flat[g * 1024 + b * 256 + tid], s);
        atomicMax(&g_fmax[(g * 4 + b) * 128 + tid], m);
    }
}

// ---------------- MLP head ----------------
__global__ __launch_bounds__(512)
void head_kernel(const float* __restrict__ Wd1, const float* __restrict__ bd1,
                 const float* __restrict__ Wd2, const float* __restrict__ bd2,
                 float* __restrict__ out) {
    __shared__ float a[1024];
    __shared__ float hd[512];
    int g = blockIdx.x, tid = threadIdx.x;
    for (int j = tid; j < 1024; j += 512) {
        int bb = j >> 8, r = j & 255;
        float v;
        if (r < 128) {
            v = g_flat[g * 1024 + bb * 256 + r];
        } else {
            unsigned int u = g_fmax[(g * 4 + bb) * 128 + (r - 128)];
            v = (u & 0x80000000u) ? __uint_as_float(u ^ 0x80000000u)
                                  : __uint_as_float(~u);
        }
        a[j] = v;
    }
    __syncthreads();
    {
        float a0 = 0.f, a1 = 0.f, a2 = 0.f, a3 = 0.f;
        #pragma unroll 4
        for (int kk = 0; kk < 1024; kk += 4) {
            a0 += a[kk + 0] * Wd1[(kk + 0) * 512 + tid];
            a1 += a[kk + 1] * Wd1[(kk + 1) * 512 + tid];
            a2 += a[kk + 2] * Wd1[(kk + 2) * 512 + tid];
            a3 += a[kk + 3] * Wd1[(kk + 3) * 512 + tid];
        }
        hd[tid] = fmaxf(a0 + a1 + a2 + a3 + bd1[tid], 0.f);
    }
    __syncthreads();
    if (tid < 320) {
        int cc = tid >> 5, l = tid & 31;
        float acc = 0.f;
        for (int kk = l; kk < 512; kk += 32) acc += hd[kk] * Wd2[kk * 10 + cc];
        #pragma unroll
        for (int o = 16; o > 0; o >>= 1) acc += __shfl_down_sync(0xffffffffu, acc, o);
        if (l == 0) out[g * 10 + cc] = acc + bd2[cc];
    }
}

// ---------------- launcher ----------------
extern "C" void kernel_launch(void* const* d_in, const int* in_sizes, int n_in,
                              void* d_out, int out_size) {
    const float* x  = (const float*)d_in[0];
    const int*   ei = (const int*)d_in[1];
    const float *Wl[4], *Wr[4], *bb[4], *gw[4], *be[4], *pp[4];
    int idx = 3;
    for (int b = 0; b < 4; b++) {
        Wl[b] = (const float*)d_in[idx++];
        Wr[b] = (const float*)d_in[idx++];
        bb[b] = (const float*)d_in[idx++];
        gw[b] = (const float*)d_in[idx++];
        be[b] = (const float*)d_in[idx++];
        pp[b] = (const float*)d_in[idx++];
    }
    const float* Wd1 = (const float*)d_in[27];
    const float* bd1 = (const float*)d_in[28];
    const float* Wd2 = (const float*)d_in[29];
    const float* bd2 = (const float*)d_in[30];
    float* out = (float*)d_out;

    cudaFuncSetAttribute(gemm_kernel, cudaFuncAttributeMaxDynamicSharedMemorySize,
                         SMEM_GEMM_BYTES);
    cudaFuncSetAttribute(mega_kernel, cudaFuncAttributeMaxDynamicSharedMemorySize,
                         MEGA_SMEM);

    csr0_kernel<<<G_, 1024>>>(ei);

    for (int b = 0; b < 4; b++) {
        int ncur = NCUR_H[b];
        int k    = KSEL_H[b];
        int nt   = G_ * ncur;
        int first = (b == 0) ? 1 : 0;
        int sel   = b & 1;
        float invnt = 1.0f / (float)nt;

        gemm_kernel<<<(nt + 63) / 64, 256, SMEM_GEMM_BYTES>>>(
            x, first, b, sel, Wl[b], Wr[b], bb[b], nt);
        bnscore_kernel<<<(nt + 7) / 8, 256>>>(gw[b], be[b], pp[b], nt, invnt, b);
        mega_kernel<<<G_, 1024, MEGA_SMEM>>>(b, ncur, k);
        gatherread_kernel<<<dim3(G_, (k + 31) / 32), 256>>>(b, ncur, k, invnt, gw[b], be[b]);
        if (b < 3)
            compact_kernel<<<(G_ * k * 32 + 255) / 256, 256>>>(ncur, k, sel);
    }
    head_kernel<<<G_, 512>>>(Wd1, bd1, Wd2, bd2, out);
}

// round 16
// speedup vs baseline: 1.0309x; 1.0046x over previous
#include <cuda_runtime.h>
#include <math.h>
#include <float.h>

// ---------------- problem constants ----------------
#define G_      32
#define EPG     16384                 // edges per graph
#define EDGES   (G_ * EPG)
#define H_      128
#define NT_MAX  32768

static const int NCUR_H[4] = {1024, 820, 656, 525};
static const int KSEL_H[4] = {820, 656, 525, 420};

// gemm smem: meanS 64x132 (row-major) + W 2x16x128 + H 2x16x64  (floats)
#define SMEM_GEMM_BYTES ((64 * 132 + 2 * 16 * 128 + 2 * 16 * 64) * 4)
// mega smem (select only)
#define MEGA_SMEM (3 * 4096 + 4096)

// ---------------- device scratch (double-buffered pooled CSR) ----------------
__device__ __align__(16) float g_bufA[NT_MAX * H_];  // pooled h (input of next block)
__device__ __align__(16) float g_bufB[NT_MAX * H_];  // conv out -> BN'd h
__device__ int   g_cnt0[NT_MAX],  g_cnt1[NT_MAX];
__device__ int   g_off0[NT_MAX],  g_off1[NT_MAX];
__device__ int   g_csrA[EDGES],   g_csrB[EDGES];
__device__ int   g_mapG[NT_MAX];
__device__ int   g_permG[NT_MAX];
__device__ float g_score[NT_MAX];
__device__ __align__(16) float g_colsum[4 * H_];
__device__ __align__(16) float g_colsq [4 * H_];
__device__ float g_flat[G_ * 1024];
__device__ unsigned int g_fmax[G_ * 4 * 128];

// ---------------- csr0 ----------------
__global__ __launch_bounds__(1024)
void csr0_kernel(const int* __restrict__ ei) {
    __shared__ int cnt[1024], off[1024], cur[1024];
    __shared__ int wsum[32];
    int g = blockIdx.x, tid = threadIdx.x;
    int lane = tid & 31, wid = tid >> 5;
    cnt[tid] = 0;
    __syncthreads();
    const int* srcp = ei + g * EPG;
    const int* dstp = ei + EDGES + g * EPG;
    for (int e = tid; e < EPG; e += 1024)
        atomicAdd(&cnt[dstp[e] - (g << 10)], 1);
    __syncthreads();
    int v = cnt[tid];
    int inc = v;
    #pragma unroll
    for (int o = 1; o < 32; o <<= 1) {
        int t = __shfl_up_sync(0xffffffffu, inc, o);
        if (lane >= o) inc += t;
    }
    if (lane == 31) wsum[wid] = inc;
    __syncthreads();
    if (wid == 0) {
        int ws = wsum[lane], wi = ws;
        #pragma unroll
        for (int o = 1; o < 32; o <<= 1) {
            int t = __shfl_up_sync(0xffffffffu, wi, o);
            if (lane >= o) wi += t;
        }
        wsum[lane] = wi - ws;
    }
    __syncthreads();
    int ex = wsum[wid] + inc - v;
    off[tid] = ex;
    g_off0[g * 1024 + tid] = g * EPG + ex;
    g_cnt0[g * 1024 + tid] = v;
    cur[tid] = 0;
    __syncthreads();
    for (int e = tid; e < EPG; e += 1024) {
        int s = srcp[e];
        int d = dstp[e] - (g << 10);
        int pos = atomicAdd(&cur[d], 1);
        g_csrA[g * EPG + off[d] + pos] = s;
    }
    int i = g * 1024 + tid;
    g_flat[i] = 0.f;
    if (i < G_ * 4 * 128) g_fmax[i] = 0u;
    if (g == 0 && tid < 4 * H_) { g_colsum[tid] = 0.f; g_colsq[tid] = 0.f; }
}

// ---------------- wide CSR compaction ----------------
__global__ __launch_bounds__(256)
void compact_kernel(int ncur, int ksel, int sel) {
    const int* ocnt = sel ? g_cnt1 : g_cnt0;
    const int* ooff = sel ? g_off1 : g_off0;
    const int* ocsr = sel ? g_csrB : g_csrA;
    int* ncnt = sel ? g_cnt0 : g_cnt1;
    int* noff = sel ? g_off0 : g_off1;
    int* ncsr = sel ? g_csrA : g_csrB;

    int n = (blockIdx.x * blockDim.x + threadIdx.x) >> 5;
    int lane = threadIdx.x & 31;
    if (n >= G_ * ksel) return;
    int g = n / ksel;
    int og = g * ncur + g_permG[n];
    int deg  = ocnt[og];
    int base = ooff[og];
    int gk = g * ksel;
    int cum = 0;
    for (int j0 = 0; j0 < deg; j0 += 32) {
        int j = j0 + lane;
        int m = -1;
        if (j < deg) m = g_mapG[ocsr[base + j]];
        unsigned int mk = __ballot_sync(0xffffffffu, m >= 0);
        if (m >= 0) {
            int pos = __popc(mk & ((1u << lane) - 1u));
            ncsr[base + cum + pos] = gk + m;
        }
        cum += __popc(mk);
    }
    if (lane == 0) { ncnt[n] = cum; noff[n] = base; }
}

// ---------------- fused gather-mean + GEMM + BN-stats (64-row tile, row-major mean) ----------------
__global__ __launch_bounds__(256, 3)
void gemm_kernel(const float* __restrict__ x, int first, int slot, int sel,
                 const float* __restrict__ Wl, const float* __restrict__ Wr,
                 const float* __restrict__ bb, int nt) {
    extern __shared__ float smem[];
    float* meanS = smem;                        // [64][132]
    float* WshB  = smem + 64 * 132;             // [2][16][128]
    float* HshB  = WshB + 2 * 16 * 128;         // [2][16][64]
    #define WSH(bf,k,c) WshB[(bf) * 2048 + (k) * 128 + (c)]
    #define HSH(bf,k,m) HshB[(bf) * 1024 + (k) * 64 + (m)]

    const int* cnti = sel ? g_cnt1 : g_cnt0;
    const int* offi = sel ? g_off1 : g_off0;
    const int* csri = sel ? g_csrB : g_csrA;

    const float* hin = first ? x : g_bufA;
    int row0 = blockIdx.x * 64;
    int tid = threadIdx.x;
    int w = tid >> 5, lane = tid & 31;
    int tx = tid & 15, ty = tid >> 4;
    int rm = ty * 4, cn = tx * 4;

    float4 pw[2];
    #pragma unroll
    for (int i = 0; i < 2; i++) {
        int idx = tid * 2 + i;
        int kk = idx >> 5, c = (idx & 31) * 4;
        pw[i] = *(const float4*)(Wl + (size_t)kk * H_ + c);
    }

    // ---- phase 1: gather means ----
    for (int i = 0; i < 8; i++) {
        int rl = w * 8 + i;
        int row = row0 + rl;
        float4 acc = make_float4(0.f, 0.f, 0.f, 0.f);
        if (row < nt) {
            int deg  = cnti[row];
            int base = offi[row];
            int j = 0;
            for (; j + 8 <= deg; j += 8) {
                int s0 = csri[base + j + 0];
                int s1 = csri[base + j + 1];
                int s2 = csri[base + j + 2];
                int s3 = csri[base + j + 3];
                int s4 = csri[base + j + 4];
                int s5 = csri[base + j + 5];
                int s6 = csri[base + j + 6];
                int s7 = csri[base + j + 7];
                float4 v0 = *((const float4*)(hin + (size_t)s0 * H_) + lane);
                float4 v1 = *((const float4*)(hin + (size_t)s1 * H_) + lane);
                float4 v2 = *((const float4*)(hin + (size_t)s2 * H_) + lane);
                float4 v3 = *((const float4*)(hin + (size_t)s3 * H_) + lane);
                float4 v4 = *((const float4*)(hin + (size_t)s4 * H_) + lane);
                float4 v5 = *((const float4*)(hin + (size_t)s5 * H_) + lane);
                float4 v6 = *((const float4*)(hin + (size_t)s6 * H_) + lane);
                float4 v7 = *((const float4*)(hin + (size_t)s7 * H_) + lane);
                acc.x += ((v0.x + v1.x) + (v2.x + v3.x)) + ((v4.x + v5.x) + (v6.x + v7.x));
                acc.y += ((v0.y + v1.y) + (v2.y + v3.y)) + ((v4.y + v5.y) + (v6.y + v7.y));
                acc.z += ((v0.z + v1.z) + (v2.z + v3.z)) + ((v4.z + v5.z) + (v6.z + v7.z));
                acc.w += ((v0.w + v1.w) + (v2.w + v3.w)) + ((v4.w + v5.w) + (v6.w + v7.w));
            }
            for (; j < deg; j++) {
                int s0 = csri[base + j];
                float4 a = *((const float4*)(hin + (size_t)s0 * H_) + lane);
                acc.x += a.x; acc.y += a.y; acc.z += a.z; acc.w += a.w;
            }
            float inv = 1.0f / fmaxf((float)deg, 1.0f);
            acc.x *= inv; acc.y *= inv; acc.z *= inv; acc.w *= inv;
        }
        *(float4*)&meanS[rl * 132 + lane * 4] = acc;
    }
    #pragma unroll
    for (int i = 0; i < 2; i++) {
        int idx = tid * 2 + i;
        int kk = idx >> 5, c = (idx & 31) * 4;
        *(float4*)&WSH(0, kk, c) = pw[i];
    }
    __syncthreads();

    float acc[4][8];
    #pragma unroll
    for (int i = 0; i < 4; i++)
        #pragma unroll
        for (int j = 0; j < 8; j++) acc[i][j] = 0.f;

    int cur = 0;
    float4 ph;

    // ---- first half: k = 0..127, A from meanS (broadcast scalar LDS) ----
    for (int kbi = 0; kbi < 8; kbi++) {
        int kwb = (kbi + 1) * 16;
        #pragma unroll
        for (int i = 0; i < 2; i++) {
            int idx = tid * 2 + i;
            int kk = idx >> 5, c = (idx & 31) * 4;
            int kw = kwb + kk;
            const float* ws = (kw < 128) ? (Wl + (size_t)kw * H_ + c)
                                         : (Wr + (size_t)(kw - 128) * H_ + c);
            pw[i] = *(const float4*)ws;
        }
        if (kbi == 7) {
            int r = tid >> 2, kc = (tid & 3) * 4;
            int row = row0 + r;
            ph = (row < nt) ? *(const float4*)(hin + (size_t)row * H_ + kc)
                            : make_float4(0.f, 0.f, 0.f, 0.f);
        }
        int kb = kbi * 16;
        #pragma unroll
        for (int kk = 0; kk < 16; kk++) {
            int kcol = kb + kk;
            float a[4];
            #pragma unroll
            for (int i = 0; i < 4; i++) a[i] = meanS[(rm + i) * 132 + kcol];
            float4 b0 = *(const float4*)&WSH(cur, kk, cn);
            float4 b1 = *(const float4*)&WSH(cur, kk, cn + 64);
            float bv[8] = {b0.x, b0.y, b0.z, b0.w, b1.x, b1.y, b1.z, b1.w};
            #pragma unroll
            for (int i = 0; i < 4; i++)
                #pragma unroll
                for (int j = 0; j < 8; j++)
                    acc[i][j] += a[i] * bv[j];
        }
        #pragma unroll
        for (int i = 0; i < 2; i++) {
            int idx = tid * 2 + i;
            int kk = idx >> 5, c = (idx & 31) * 4;
            *(float4*)&WSH(cur ^ 1, kk, c) = pw[i];
        }
        if (kbi == 7) {
            int r = tid >> 2, kc = (tid & 3) * 4;
            HSH(cur ^ 1, kc + 0, r) = ph.x;
            HSH(cur ^ 1, kc + 1, r) = ph.y;
            HSH(cur ^ 1, kc + 2, r) = ph.z;
            HSH(cur ^ 1, kc + 3, r) = ph.w;
        }
        __syncthreads();
        cur ^= 1;
    }

    // ---- second half: k = 128..255, A from Hsh ----
    for (int kbi = 8; kbi < 16; kbi++) {
        if (kbi < 15) {
            int kwb = (kbi + 1) * 16;
            int hb  = (kbi + 1 - 8) * 16;
            #pragma unroll
            for (int i = 0; i < 2; i++) {
                int idx = tid * 2 + i;
                int kk = idx >> 5, c = (idx & 31) * 4;
                pw[i] = *(const float4*)(Wr + (size_t)(kwb + kk - 128) * H_ + c);
            }
            int r = tid >> 2, kc = (tid & 3) * 4;
            int row = row0 + r;
            ph = (row < nt) ? *(const float4*)(hin + (size_t)row * H_ + hb + kc)
                            : make_float4(0.f, 0.f, 0.f, 0.f);
        }
        #pragma unroll
        for (int kk = 0; kk < 16; kk++) {
            float4 a0 = *(const float4*)&HSH(cur, kk, rm);
            float4 b0 = *(const float4*)&WSH(cur, kk, cn);
            float4 b1 = *(const float4*)&WSH(cur, kk, cn + 64);
            float a[4] = {a0.x, a0.y, a0.z, a0.w};
            float bv[8] = {b0.x, b0.y, b0.z, b0.w, b1.x, b1.y, b1.z, b1.w};
            #pragma unroll
            for (int i = 0; i < 4; i++)
                #pragma unroll
                for (int j = 0; j < 8; j++)
                    acc[i][j] += a[i] * bv[j];
        }
        if (kbi < 15) {
            #pragma unroll
            for (int i = 0; i < 2; i++) {
                int idx = tid * 2 + i;
                int kk = idx >> 5, c = (idx & 31) * 4;
                *(float4*)&WSH(cur ^ 1, kk, c) = pw[i];
            }
            int r = tid >> 2, kc = (tid & 3) * 4;
            HSH(cur ^ 1, kc + 0, r) = ph.x;
            HSH(cur ^ 1, kc + 1, r) = ph.y;
            HSH(cur ^ 1, kc + 2, r) = ph.z;
            HSH(cur ^ 1, kc + 3, r) = ph.w;
        }
        __syncthreads();
        cur ^= 1;
    }

    // ---- epilogue ----
    float4 bia0 = *(const float4*)&bb[cn];
    float4 bia1 = *(const float4*)&bb[cn + 64];
    float bias[8] = {bia0.x, bia0.y, bia0.z, bia0.w, bia1.x, bia1.y, bia1.z, bia1.w};
    float psum[8], psq[8];
    #pragma unroll
    for (int j = 0; j < 8; j++) { psum[j] = 0.f; psq[j] = 0.f; }
    #pragma unroll
    for (int i = 0; i < 4; i++) {
        int row = row0 + rm + i;
        if (row < nt) {
            float v[8];
            #pragma unroll
            for (int j = 0; j < 8; j++) {
                v[j] = acc[i][j] + bias[j];
                psum[j] += v[j];
                psq[j]  += v[j] * v[j];
            }
            *(float4*)(g_bufB + (size_t)row * H_ + cn)      = make_float4(v[0], v[1], v[2], v[3]);
            *(float4*)(g_bufB + (size_t)row * H_ + cn + 64) = make_float4(v[4], v[5], v[6], v[7]);
        }
    }
    __syncthreads();
    float* sumS = smem;           // [16][128]
    float* sqS  = smem + 2048;    // [16][128]
    #pragma unroll
    for (int j = 0; j < 4; j++) {
        sumS[ty * 128 + cn + j]      = psum[j];
        sumS[ty * 128 + cn + 64 + j] = psum[4 + j];
        sqS [ty * 128 + cn + j]      = psq[j];
        sqS [ty * 128 + cn + 64 + j] = psq[4 + j];
    }
    __syncthreads();
    if (tid < 128) {
        float s = 0.f, q = 0.f;
        #pragma unroll
        for (int t = 0; t < 16; t++) {
            s += sumS[t * 128 + tid];
            q += sqS [t * 128 + tid];
        }
        atomicAdd(&g_colsum[slot * H_ + tid], s);
        atomicAdd(&g_colsq [slot * H_ + tid], q);
    }
    #undef WSH
    #undef HSH
}

// ---------------- wide BN + ReLU + score (with writeback) ----------------
__global__ __launch_bounds__(256)
void bnscore_kernel(const float* __restrict__ gw, const float* __restrict__ be,
                    const float* __restrict__ p, int nt, float invnt, int slot) {
    int row = blockIdx.x * 8 + (threadIdx.x >> 5);
    int lane = threadIdx.x & 31;
    if (row >= nt) return;
    int c = lane * 4;
    float4 h  = *(const float4*)(g_bufB + (size_t)row * H_ + c);
    float4 cs = *(const float4*)&g_colsum[slot * H_ + c];
    float4 cq = *(const float4*)&g_colsq [slot * H_ + c];
    float4 gv = *(const float4*)&gw[c];
    float4 bv = *(const float4*)&be[c];
    float4 pv = *(const float4*)&p[c];
    float hh[4]  = {h.x, h.y, h.z, h.w};
    float css[4] = {cs.x, cs.y, cs.z, cs.w};
    float cqq[4] = {cq.x, cq.y, cq.z, cq.w};
    float gg[4]  = {gv.x, gv.y, gv.z, gv.w};
    float bbv[4] = {bv.x, bv.y, bv.z, bv.w};
    float pp[4]  = {pv.x, pv.y, pv.z, pv.w};
    float out[4];
    float dot = 0.f, pn = 0.f;
    #pragma unroll
    for (int j = 0; j < 4; j++) {
        float mu = css[j] * invnt;
        float var = cqq[j] * invnt - mu * mu;
        float r = rsqrtf(var + 1e-5f);
        float v = (hh[j] - mu) * r * gg[j] + bbv[j];
        v = fmaxf(v, 0.f);
        out[j] = v;
        dot += v * pp[j];
        pn  += pp[j] * pp[j];
    }
    *(float4*)(g_bufB + (size_t)row * H_ + c) = make_float4(out[0], out[1], out[2], out[3]);
    #pragma unroll
    for (int o = 16; o > 0; o >>= 1) {
        dot += __shfl_down_sync(0xffffffffu, dot, o);
        pn  += __shfl_down_sync(0xffffffffu, pn, o);
    }
    if (lane == 0) g_score[row] = dot * rsqrtf(pn);
}

// ---------------- mega: radix-select -> publish map/perm ----------------
__global__ __launch_bounds__(1024)
void mega_kernel(int b, int ncur, int ksel) {
    extern __shared__ char smx[];
    int*   s_perm  = (int*)(smx);
    int*   s_map   = (int*)(smx + 4096);
    int*   s_red   = (int*)(smx + 8192);

    int g = blockIdx.x, tid = threadIdx.x;
    int lane = tid & 31, wid = tid >> 5;

    float myscore = (tid < ncur) ? g_score[g * ncur + tid] : -FLT_MAX;
    unsigned int key = 0u;
    if (tid < ncur) {
        unsigned int u = __float_as_uint(myscore);
        key = (u & 0x80000000u) ? ~u : (u | 0x80000000u);
    }

    int* hist  = s_red;
    int* hist2 = hist + 256;
    int* wtot  = hist + 512;
    int* s_sel = hist + 544;
    unsigned int prefixK = 0u, pmask = 0u;
    int remaining = ksel;
    #pragma unroll
    for (int pass = 0; pass < 4; pass++) {
        int shift = 24 - pass * 8;
        if (tid < 256) hist[tid] = 0;
        __syncthreads();
        if ((key & pmask) == prefixK)
            atomicAdd(&hist[(key >> shift) & 255u], 1);
        __syncthreads();
        int inc = 0;
        if (tid < 256) {
            inc = hist[255 - tid];
            #pragma unroll
            for (int o = 1; o < 32; o <<= 1) {
                int t = __shfl_up_sync(0xffffffffu, inc, o);
                if (lane >= o) inc += t;
            }
            if (lane == 31) wtot[tid >> 5] = inc;
        }
        __syncthreads();
        if (tid < 256) {
            int w8 = tid >> 5, add = 0;
            for (int q = 0; q < w8; q++) add += wtot[q];
            hist2[tid] = inc + add;
        }
        __syncthreads();
        if (tid < 256) {
            int sfx = hist2[tid];
            int above = (tid == 0) ? 0 : hist2[tid - 1];
            if (sfx >= remaining && above < remaining) {
                s_sel[0] = 255 - tid;
                s_sel[1] = above;
            }
        }
        __syncthreads();
        prefixK |= ((unsigned int)s_sel[0]) << shift;
        pmask   |= 255u << shift;
        remaining -= s_sel[1];
        __syncthreads();
    }
    unsigned int T = prefixK;
    int R = remaining;

    int strict = (key > T) ? 1 : 0;
    int tie    = (key == T) ? 1 : 0;
    int pk = strict | (tie << 16);
    int incs = pk;
    #pragma unroll
    for (int o = 1; o < 32; o <<= 1) {
        int t = __shfl_up_sync(0xffffffffu, incs, o);
        if (lane >= o) incs += t;
    }
    int* wsum = hist;
    if (lane == 31) wsum[wid] = incs;
    __syncthreads();
    if (wid == 0) {
        int ws = wsum[lane], wi = ws;
        #pragma unroll
        for (int o = 1; o < 32; o <<= 1) {
            int t = __shfl_up_sync(0xffffffffu, wi, o);
            if (lane >= o) wi += t;
        }
        wsum[lane] = wi - ws;
    }
    __syncthreads();
    int before = wsum[wid] + incs - pk;
    int sk_before  = before & 0xFFFF;
    int tie_before = before >> 16;
    int acc_f = strict | (tie & (tie_before < R ? 1 : 0));
    int newid = sk_before + (tie_before < R ? tie_before : R);
    s_map[tid] = acc_f ? newid : -1;
    if (acc_f) s_perm[newid] = tid;
    __syncthreads();

    if (tid < ncur && b < 3) g_mapG[g * ncur + tid] = s_map[tid];
    if (tid < ksel) g_permG[g * ksel + tid] = s_perm[tid];
}

// ---------------- wide gather + tanh gate + readout partials ----------------
__global__ __launch_bounds__(256)
void gatherread_kernel(int b, int ncur, int ksel) {
    __shared__ float ssum[8][128];
    __shared__ unsigned int smax[8][128];
    int g = blockIdx.x;
    int row0 = blockIdx.y * 32;
    int tid = threadIdx.x, wid = tid >> 5, lane = tid & 31;
    int c = lane * 4;
    float4 rsum = make_float4(0.f, 0.f, 0.f, 0.f);
    float4 rmax = make_float4(-FLT_MAX, -FLT_MAX, -FLT_MAX, -FLT_MAX);
    #pragma unroll
    for (int r = 0; r < 4; r++) {
        int nw = row0 + wid * 4 + r;
        if (nw < ksel) {
            int old = g_permG[g * ksel + nw];
            float t = tanhf(g_score[g * ncur + old]);
            float4 h = *((const float4*)(g_bufB + (size_t)(g * ncur + old) * H_) + lane);
            h.x *= t; h.y *= t; h.z *= t; h.w *= t;
            if (b < 3) *((float4*)(g_bufA + (size_t)(g * ksel + nw) * H_) + lane) = h;
            rsum.x += h.x; rsum.y += h.y; rsum.z += h.z; rsum.w += h.w;
            rmax.x = fmaxf(rmax.x, h.x); rmax.y = fmaxf(rmax.y, h.y);
            rmax.z = fmaxf(rmax.z, h.z); rmax.w = fmaxf(rmax.w, h.w);
        }
    }
    *(float4*)&ssum[wid][c] = rsum;
    {
        unsigned int ux = __float_as_uint(rmax.x);
        unsigned int uy = __float_as_uint(rmax.y);
        unsigned int uz = __float_as_uint(rmax.z);
        unsigned int uw = __float_as_uint(rmax.w);
        smax[wid][c + 0] = (ux & 0x80000000u) ? ~ux : (ux | 0x80000000u);
        smax[wid][c + 1] = (uy & 0x80000000u) ? ~uy : (uy | 0x80000000u);
        smax[wid][c + 2] = (uz & 0x80000000u) ? ~uz : (uz | 0x80000000u);
        smax[wid][c + 3] = (uw & 0x80000000u) ? ~uw : (uw | 0x80000000u);
    }
    __syncthreads();
    if (tid < 128) {
        float s = 0.f;
        unsigned int m = 0u;
        #pragma unroll
        for (int w = 0; w < 8; w++) {
            s += ssum[w][tid];
            m = max(m, smax[w][tid]);
        }
        atomicAdd(&g_flat[g * 1024 + b * 256 + tid], s);
        atomicMax(&g_fmax[(g * 4 + b) * 128 + tid], m);
    }
}

// ---------------- MLP head ----------------
__global__ __launch_bounds__(512)
void head_kernel(const float* __restrict__ Wd1, const float* __restrict__ bd1,
                 const float* __restrict__ Wd2, const float* __restrict__ bd2,
                 float* __restrict__ out) {
    __shared__ float a[1024];
    __shared__ float hd[512];
    int g = blockIdx.x, tid = threadIdx.x;
    for (int j = tid; j < 1024; j += 512) {
        int bb = j >> 8, r = j & 255;
        float v;
        if (r < 128) {
            v = g_flat[g * 1024 + bb * 256 + r];
        } else {
            unsigned int u = g_fmax[(g * 4 + bb) * 128 + (r - 128)];
            v = (u & 0x80000000u) ? __uint_as_float(u ^ 0x80000000u)
                                  : __uint_as_float(~u);
        }
        a[j] = v;
    }
    __syncthreads();
    {
        float a0 = 0.f, a1 = 0.f, a2 = 0.f, a3 = 0.f;
        #pragma unroll 4
        for (int kk = 0; kk < 1024; kk += 4) {
            a0 += a[kk + 0] * Wd1[(kk + 0) * 512 + tid];
            a1 += a[kk + 1] * Wd1[(kk + 1) * 512 + tid];
            a2 += a[kk + 2] * Wd1[(kk + 2) * 512 + tid];
            a3 += a[kk + 3] * Wd1[(kk + 3) * 512 + tid];
        }
        hd[tid] = fmaxf(a0 + a1 + a2 + a3 + bd1[tid], 0.f);
    }
    __syncthreads();
    if (tid < 320) {
        int cc = tid >> 5, l = tid & 31;
        float acc = 0.f;
        for (int kk = l; kk < 512; kk += 32) acc += hd[kk] * Wd2[kk * 10 + cc];
        #pragma unroll
        for (int o = 16; o > 0; o >>= 1) acc += __shfl_down_sync(0xffffffffu, acc, o);
        if (l == 0) out[g * 10 + cc] = acc + bd2[cc];
    }
}

// ---------------- launcher ----------------
extern "C" void kernel_launch(void* const* d_in, const int* in_sizes, int n_in,
                              void* d_out, int out_size) {
    const float* x  = (const float*)d_in[0];
    const int*   ei = (const int*)d_in[1];
    const float *Wl[4], *Wr[4], *bb[4], *gw[4], *be[4], *pp[4];
    int idx = 3;
    for (int b = 0; b < 4; b++) {
        Wl[b] = (const float*)d_in[idx++];
        Wr[b] = (const float*)d_in[idx++];
        bb[b] = (const float*)d_in[idx++];
        gw[b] = (const float*)d_in[idx++];
        be[b] = (const float*)d_in[idx++];
        pp[b] = (const float*)d_in[idx++];
    }
    const float* Wd1 = (const float*)d_in[27];
    const float* bd1 = (const float*)d_in[28];
    const float* Wd2 = (const float*)d_in[29];
    const float* bd2 = (const float*)d_in[30];
    float* out = (float*)d_out;

    // lazily created on the first (non-captured) correctness call; reused thereafter
    static cudaStream_t s2 = nullptr;
    static cudaEvent_t evFork = nullptr, evJoin = nullptr;
    if (s2 == nullptr) {
        cudaStreamCreateWithFlags(&s2, cudaStreamNonBlocking);
        cudaEventCreateWithFlags(&evFork, cudaEventDisableTiming);
        cudaEventCreateWithFlags(&evJoin, cudaEventDisableTiming);
        cudaFuncSetAttribute(gemm_kernel, cudaFuncAttributeMaxDynamicSharedMemorySize,
                             SMEM_GEMM_BYTES);
        cudaFuncSetAttribute(mega_kernel, cudaFuncAttributeMaxDynamicSharedMemorySize,
                             MEGA_SMEM);
    }

    csr0_kernel<<<G_, 1024>>>(ei);

    for (int b = 0; b < 4; b++) {
        int ncur = NCUR_H[b];
        int k    = KSEL_H[b];
        int nt   = G_ * ncur;
        int first = (b == 0) ? 1 : 0;
        int sel   = b & 1;
        float invnt = 1.0f / (float)nt;

        gemm_kernel<<<(nt + 63) / 64, 256, SMEM_GEMM_BYTES>>>(
            x, first, b, sel, Wl[b], Wr[b], bb[b], nt);
        bnscore_kernel<<<(nt + 7) / 8, 256>>>(gw[b], be[b], pp[b], nt, invnt, b);
        mega_kernel<<<G_, 1024, MEGA_SMEM>>>(b, ncur, k);
        if (b < 3) {
            // fork: compact on s2 in parallel with gatherread on the main stream
            cudaEventRecord(evFork, 0);
            cudaStreamWaitEvent(s2, evFork, 0);
            compact_kernel<<<(G_ * k * 32 + 255) / 256, 256, 0, s2>>>(ncur, k, sel);
            cudaEventRecord(evJoin, s2);
            gatherread_kernel<<<dim3(G_, (k + 31) / 32), 256>>>(b, ncur, k);
            cudaStreamWaitEvent(0, evJoin, 0);
        } else {
            gatherread_kernel<<<dim3(G_, (k + 31) / 32), 256>>>(b, ncur, k);
        }
    }
    head_kernel<<<G_, 512>>>(Wd1, bd1, Wd2, bd2, out);
}

// round 17
// speedup vs baseline: 1.0499x; 1.0184x over previous
#include <cuda_runtime.h>
#include <math.h>
#include <float.h>

// ---------------- problem constants ----------------
#define G_      32
#define EPG     16384                 // edges per graph
#define EDGES   (G_ * EPG)
#define H_      128
#define NT_MAX  32768

static const int NCUR_H[4] = {1024, 820, 656, 525};
static const int KSEL_H[4] = {820, 656, 525, 420};

// gemm smem: meanS 64x132 (row-major) + W 2x16x128 + H 2x16x64  (floats)
#define SMEM_GEMM_BYTES ((64 * 132 + 2 * 16 * 128 + 2 * 16 * 64) * 4)
// mega smem (select only)
#define MEGA_SMEM (3 * 4096 + 4096)

// ---------------- device scratch (double-buffered pooled CSR) ----------------
__device__ __align__(16) float g_bufA[NT_MAX * H_];  // pooled h (input of next block)
__device__ __align__(16) float g_bufB[NT_MAX * H_];  // conv out -> BN'd h
__device__ int   g_cnt0[NT_MAX],  g_cnt1[NT_MAX];
__device__ int   g_off0[NT_MAX],  g_off1[NT_MAX];
__device__ int   g_csrA[EDGES],   g_csrB[EDGES];
__device__ int   g_mapG[NT_MAX];
__device__ int   g_permG[NT_MAX];
__device__ float g_score[NT_MAX];
__device__ __align__(16) float g_colsum[4 * H_];
__device__ __align__(16) float g_colsq [4 * H_];
__device__ float g_flat[G_ * 1024];
__device__ unsigned int g_fmax[G_ * 4 * 128];

// ---------------- csr0 ----------------
__global__ __launch_bounds__(1024)
void csr0_kernel(const int* __restrict__ ei) {
    __shared__ int cnt[1024], off[1024], cur[1024];
    __shared__ int wsum[32];
    int g = blockIdx.x, tid = threadIdx.x;
    int lane = tid & 31, wid = tid >> 5;
    cnt[tid] = 0;
    __syncthreads();
    const int* srcp = ei + g * EPG;
    const int* dstp = ei + EDGES + g * EPG;
    for (int e = tid; e < EPG; e += 1024)
        atomicAdd(&cnt[dstp[e] - (g << 10)], 1);
    __syncthreads();
    int v = cnt[tid];
    int inc = v;
    #pragma unroll
    for (int o = 1; o < 32; o <<= 1) {
        int t = __shfl_up_sync(0xffffffffu, inc, o);
        if (lane >= o) inc += t;
    }
    if (lane == 31) wsum[wid] = inc;
    __syncthreads();
    if (wid == 0) {
        int ws = wsum[lane], wi = ws;
        #pragma unroll
        for (int o = 1; o < 32; o <<= 1) {
            int t = __shfl_up_sync(0xffffffffu, wi, o);
            if (lane >= o) wi += t;
        }
        wsum[lane] = wi - ws;
    }
    __syncthreads();
    int ex = wsum[wid] + inc - v;
    off[tid] = ex;
    g_off0[g * 1024 + tid] = g * EPG + ex;
    g_cnt0[g * 1024 + tid] = v;
    cur[tid] = 0;
    __syncthreads();
    for (int e = tid; e < EPG; e += 1024) {
        int s = srcp[e];
        int d = dstp[e] - (g << 10);
        int pos = atomicAdd(&cur[d], 1);
        g_csrA[g * EPG + off[d] + pos] = s;
    }
    int i = g * 1024 + tid;
    g_flat[i] = 0.f;
    if (i < G_ * 4 * 128) g_fmax[i] = 0u;
    if (g == 0 && tid < 4 * H_) { g_colsum[tid] = 0.f; g_colsq[tid] = 0.f; }
}

// ---------------- fused gather-mean + GEMM + BN-stats (64-row tile, row-major mean) ----------------
__global__ __launch_bounds__(256, 3)
void gemm_kernel(const float* __restrict__ x, int first, int slot, int sel,
                 const float* __restrict__ Wl, const float* __restrict__ Wr,
                 const float* __restrict__ bb, int nt) {
    extern __shared__ float smem[];
    float* meanS = smem;                        // [64][132]
    float* WshB  = smem + 64 * 132;             // [2][16][128]
    float* HshB  = WshB + 2 * 16 * 128;         // [2][16][64]
    #define WSH(bf,k,c) WshB[(bf) * 2048 + (k) * 128 + (c)]
    #define HSH(bf,k,m) HshB[(bf) * 1024 + (k) * 64 + (m)]

    const int* cnti = sel ? g_cnt1 : g_cnt0;
    const int* offi = sel ? g_off1 : g_off0;
    const int* csri = sel ? g_csrB : g_csrA;

    const float* hin = first ? x : g_bufA;
    int row0 = blockIdx.x * 64;
    int tid = threadIdx.x;
    int w = tid >> 5, lane = tid & 31;
    int tx = tid & 15, ty = tid >> 4;
    int rm = ty * 4, cn = tx * 4;

    float4 pw[2];
    #pragma unroll
    for (int i = 0; i < 2; i++) {
        int idx = tid * 2 + i;
        int kk = idx >> 5, c = (idx & 31) * 4;
        pw[i] = *(const float4*)(Wl + (size_t)kk * H_ + c);
    }

    // ---- phase 1: gather means ----
    for (int i = 0; i < 8; i++) {
        int rl = w * 8 + i;
        int row = row0 + rl;
        float4 acc = make_float4(0.f, 0.f, 0.f, 0.f);
        if (row < nt) {
            int deg  = cnti[row];
            int base = offi[row];
            int j = 0;
            for (; j + 8 <= deg; j += 8) {
                int s0 = csri[base + j + 0];
                int s1 = csri[base + j + 1];
                int s2 = csri[base + j + 2];
                int s3 = csri[base + j + 3];
                int s4 = csri[base + j + 4];
                int s5 = csri[base + j + 5];
                int s6 = csri[base + j + 6];
                int s7 = csri[base + j + 7];
                float4 v0 = *((const float4*)(hin + (size_t)s0 * H_) + lane);
                float4 v1 = *((const float4*)(hin + (size_t)s1 * H_) + lane);
                float4 v2 = *((const float4*)(hin + (size_t)s2 * H_) + lane);
                float4 v3 = *((const float4*)(hin + (size_t)s3 * H_) + lane);
                float4 v4 = *((const float4*)(hin + (size_t)s4 * H_) + lane);
                float4 v5 = *((const float4*)(hin + (size_t)s5 * H_) + lane);
                float4 v6 = *((const float4*)(hin + (size_t)s6 * H_) + lane);
                float4 v7 = *((const float4*)(hin + (size_t)s7 * H_) + lane);
                acc.x += ((v0.x + v1.x) + (v2.x + v3.x)) + ((v4.x + v5.x) + (v6.x + v7.x));
                acc.y += ((v0.y + v1.y) + (v2.y + v3.y)) + ((v4.y + v5.y) + (v6.y + v7.y));
                acc.z += ((v0.z + v1.z) + (v2.z + v3.z)) + ((v4.z + v5.z) + (v6.z + v7.z));
                acc.w += ((v0.w + v1.w) + (v2.w + v3.w)) + ((v4.w + v5.w) + (v6.w + v7.w));
            }
            for (; j < deg; j++) {
                int s0 = csri[base + j];
                float4 a = *((const float4*)(hin + (size_t)s0 * H_) + lane);
                acc.x += a.x; acc.y += a.y; acc.z += a.z; acc.w += a.w;
            }
            float inv = 1.0f / fmaxf((float)deg, 1.0f);
            acc.x *= inv; acc.y *= inv; acc.z *= inv; acc.w *= inv;
        }
        *(float4*)&meanS[rl * 132 + lane * 4] = acc;
    }
    #pragma unroll
    for (int i = 0; i < 2; i++) {
        int idx = tid * 2 + i;
        int kk = idx >> 5, c = (idx & 31) * 4;
        *(float4*)&WSH(0, kk, c) = pw[i];
    }
    __syncthreads();

    float acc[4][8];
    #pragma unroll
    for (int i = 0; i < 4; i++)
        #pragma unroll
        for (int j = 0; j < 8; j++) acc[i][j] = 0.f;

    int cur = 0;
    float4 ph;

    // ---- first half: k = 0..127, A from meanS ----
    for (int kbi = 0; kbi < 8; kbi++) {
        int kwb = (kbi + 1) * 16;
        #pragma unroll
        for (int i = 0; i < 2; i++) {
            int idx = tid * 2 + i;
            int kk = idx >> 5, c = (idx & 31) * 4;
            int kw = kwb + kk;
            const float* ws = (kw < 128) ? (Wl + (size_t)kw * H_ + c)
                                         : (Wr + (size_t)(kw - 128) * H_ + c);
            pw[i] = *(const float4*)ws;
        }
        if (kbi == 7) {
            int r = tid >> 2, kc = (tid & 3) * 4;
            int row = row0 + r;
            ph = (row < nt) ? *(const float4*)(hin + (size_t)row * H_ + kc)
                            : make_float4(0.f, 0.f, 0.f, 0.f);
        }
        int kb = kbi * 16;
        #pragma unroll
        for (int kk = 0; kk < 16; kk++) {
            int kcol = kb + kk;
            float a[4];
            #pragma unroll
            for (int i = 0; i < 4; i++) a[i] = meanS[(rm + i) * 132 + kcol];
            float4 b0 = *(const float4*)&WSH(cur, kk, cn);
            float4 b1 = *(const float4*)&WSH(cur, kk, cn + 64);
            float bv[8] = {b0.x, b0.y, b0.z, b0.w, b1.x, b1.y, b1.z, b1.w};
            #pragma unroll
            for (int i = 0; i < 4; i++)
                #pragma unroll
                for (int j = 0; j < 8; j++)
                    acc[i][j] += a[i] * bv[j];
        }
        #pragma unroll
        for (int i = 0; i < 2; i++) {
            int idx = tid * 2 + i;
            int kk = idx >> 5, c = (idx & 31) * 4;
            *(float4*)&WSH(cur ^ 1, kk, c) = pw[i];
        }
        if (kbi == 7) {
            int r = tid >> 2, kc = (tid & 3) * 4;
            HSH(cur ^ 1, kc + 0, r) = ph.x;
            HSH(cur ^ 1, kc + 1, r) = ph.y;
            HSH(cur ^ 1, kc + 2, r) = ph.z;
            HSH(cur ^ 1, kc + 3, r) = ph.w;
        }
        __syncthreads();
        cur ^= 1;
    }

    // ---- second half: k = 128..255, A from Hsh ----
    for (int kbi = 8; kbi < 16; kbi++) {
        if (kbi < 15) {
            int kwb = (kbi + 1) * 16;
            int hb  = (kbi + 1 - 8) * 16;
            #pragma unroll
            for (int i = 0; i < 2; i++) {
                int idx = tid * 2 + i;
                int kk = idx >> 5, c = (idx & 31) * 4;
                pw[i] = *(const float4*)(Wr + (size_t)(kwb + kk - 128) * H_ + c);
            }
            int r = tid >> 2, kc = (tid & 3) * 4;
            int row = row0 + r;
            ph = (row < nt) ? *(const float4*)(hin + (size_t)row * H_ + hb + kc)
                            : make_float4(0.f, 0.f, 0.f, 0.f);
        }
        #pragma unroll
        for (int kk = 0; kk < 16; kk++) {
            float4 a0 = *(const float4*)&HSH(cur, kk, rm);
            float4 b0 = *(const float4*)&WSH(cur, kk, cn);
            float4 b1 = *(const float4*)&WSH(cur, kk, cn + 64);
            float a[4] = {a0.x, a0.y, a0.z, a0.w};
            float bv[8] = {b0.x, b0.y, b0.z, b0.w, b1.x, b1.y, b1.z, b1.w};
            #pragma unroll
            for (int i = 0; i < 4; i++)
                #pragma unroll
                for (int j = 0; j < 8; j++)
                    acc[i][j] += a[i] * bv[j];
        }
        if (kbi < 15) {
            #pragma unroll
            for (int i = 0; i < 2; i++) {
                int idx = tid * 2 + i;
                int kk = idx >> 5, c = (idx & 31) * 4;
                *(float4*)&WSH(cur ^ 1, kk, c) = pw[i];
            }
            int r = tid >> 2, kc = (tid & 3) * 4;
            HSH(cur ^ 1, kc + 0, r) = ph.x;
            HSH(cur ^ 1, kc + 1, r) = ph.y;
            HSH(cur ^ 1, kc + 2, r) = ph.z;
            HSH(cur ^ 1, kc + 3, r) = ph.w;
        }
        __syncthreads();
        cur ^= 1;
    }

    // ---- epilogue ----
    float4 bia0 = *(const float4*)&bb[cn];
    float4 bia1 = *(const float4*)&bb[cn + 64];
    float bias[8] = {bia0.x, bia0.y, bia0.z, bia0.w, bia1.x, bia1.y, bia1.z, bia1.w};
    float psum[8], psq[8];
    #pragma unroll
    for (int j = 0; j < 8; j++) { psum[j] = 0.f; psq[j] = 0.f; }
    #pragma unroll
    for (int i = 0; i < 4; i++) {
        int row = row0 + rm + i;
        if (row < nt) {
            float v[8];
            #pragma unroll
            for (int j = 0; j < 8; j++) {
                v[j] = acc[i][j] + bias[j];
                psum[j] += v[j];
                psq[j]  += v[j] * v[j];
            }
            *(float4*)(g_bufB + (size_t)row * H_ + cn)      = make_float4(v[0], v[1], v[2], v[3]);
            *(float4*)(g_bufB + (size_t)row * H_ + cn + 64) = make_float4(v[4], v[5], v[6], v[7]);
        }
    }
    __syncthreads();
    float* sumS = smem;           // [16][128]
    float* sqS  = smem + 2048;    // [16][128]
    #pragma unroll
    for (int j = 0; j < 4; j++) {
        sumS[ty * 128 + cn + j]      = psum[j];
        sumS[ty * 128 + cn + 64 + j] = psum[4 + j];
        sqS [ty * 128 + cn + j]      = psq[j];
        sqS [ty * 128 + cn + 64 + j] = psq[4 + j];
    }
    __syncthreads();
    if (tid < 128) {
        float s = 0.f, q = 0.f;
        #pragma unroll
        for (int t = 0; t < 16; t++) {
            s += sumS[t * 128 + tid];
            q += sqS [t * 128 + tid];
        }
        atomicAdd(&g_colsum[slot * H_ + tid], s);
        atomicAdd(&g_colsq [slot * H_ + tid], q);
    }
    #undef WSH
    #undef HSH
}

// ---------------- wide BN + ReLU + score (with writeback) ----------------
__global__ __launch_bounds__(256)
void bnscore_kernel(const float* __restrict__ gw, const float* __restrict__ be,
                    const float* __restrict__ p, int nt, float invnt, int slot) {
    int row = blockIdx.x * 8 + (threadIdx.x >> 5);
    int lane = threadIdx.x & 31;
    if (row >= nt) return;
    int c = lane * 4;
    float4 h  = *(const float4*)(g_bufB + (size_t)row * H_ + c);
    float4 cs = *(const float4*)&g_colsum[slot * H_ + c];
    float4 cq = *(const float4*)&g_colsq [slot * H_ + c];
    float4 gv = *(const float4*)&gw[c];
    float4 bv = *(const float4*)&be[c];
    float4 pv = *(const float4*)&p[c];
    float hh[4]  = {h.x, h.y, h.z, h.w};
    float css[4] = {cs.x, cs.y, cs.z, cs.w};
    float cqq[4] = {cq.x, cq.y, cq.z, cq.w};
    float gg[4]  = {gv.x, gv.y, gv.z, gv.w};
    float bbv[4] = {bv.x, bv.y, bv.z, bv.w};
    float pp[4]  = {pv.x, pv.y, pv.z, pv.w};
    float out[4];
    float dot = 0.f, pn = 0.f;
    #pragma unroll
    for (int j = 0; j < 4; j++) {
        float mu = css[j] * invnt;
        float var = cqq[j] * invnt - mu * mu;
        float r = rsqrtf(var + 1e-5f);
        float v = (hh[j] - mu) * r * gg[j] + bbv[j];
        v = fmaxf(v, 0.f);
        out[j] = v;
        dot += v * pp[j];
        pn  += pp[j] * pp[j];
    }
    *(float4*)(g_bufB + (size_t)row * H_ + c) = make_float4(out[0], out[1], out[2], out[3]);
    #pragma unroll
    for (int o = 16; o > 0; o >>= 1) {
        dot += __shfl_down_sync(0xffffffffu, dot, o);
        pn  += __shfl_down_sync(0xffffffffu, pn, o);
    }
    if (lane == 0) g_score[row] = dot * rsqrtf(pn);
}

// ---------------- mega: radix-select -> publish map/perm ----------------
__global__ __launch_bounds__(1024)
void mega_kernel(int b, int ncur, int ksel) {
    extern __shared__ char smx[];
    int*   s_perm  = (int*)(smx);
    int*   s_map   = (int*)(smx + 4096);
    int*   s_red   = (int*)(smx + 8192);

    int g = blockIdx.x, tid = threadIdx.x;
    int lane = tid & 31, wid = tid >> 5;

    float myscore = (tid < ncur) ? g_score[g * ncur + tid] : -FLT_MAX;
    unsigned int key = 0u;
    if (tid < ncur) {
        unsigned int u = __float_as_uint(myscore);
        key = (u & 0x80000000u) ? ~u : (u | 0x80000000u);
    }

    int* hist  = s_red;
    int* hist2 = hist + 256;
    int* wtot  = hist + 512;
    int* s_sel = hist + 544;
    unsigned int prefixK = 0u, pmask = 0u;
    int remaining = ksel;
    #pragma unroll
    for (int pass = 0; pass < 4; pass++) {
        int shift = 24 - pass * 8;
        if (tid < 256) hist[tid] = 0;
        __syncthreads();
        if ((key & pmask) == prefixK)
            atomicAdd(&hist[(key >> shift) & 255u], 1);
        __syncthreads();
        int inc = 0;
        if (tid < 256) {
            inc = hist[255 - tid];
            #pragma unroll
            for (int o = 1; o < 32; o <<= 1) {
                int t = __shfl_up_sync(0xffffffffu, inc, o);
                if (lane >= o) inc += t;
            }
            if (lane == 31) wtot[tid >> 5] = inc;
        }
        __syncthreads();
        if (tid < 256) {
            int w8 = tid >> 5, add = 0;
            for (int q = 0; q < w8; q++) add += wtot[q];
            hist2[tid] = inc + add;
        }
        __syncthreads();
        if (tid < 256) {
            int sfx = hist2[tid];
            int above = (tid == 0) ? 0 : hist2[tid - 1];
            if (sfx >= remaining && above < remaining) {
                s_sel[0] = 255 - tid;
                s_sel[1] = above;
            }
        }
        __syncthreads();
        prefixK |= ((unsigned int)s_sel[0]) << shift;
        pmask   |= 255u << shift;
        remaining -= s_sel[1];
        __syncthreads();
    }
    unsigned int T = prefixK;
    int R = remaining;

    int strict = (key > T) ? 1 : 0;
    int tie    = (key == T) ? 1 : 0;
    int pk = strict | (tie << 16);
    int incs = pk;
    #pragma unroll
    for (int o = 1; o < 32; o <<= 1) {
        int t = __shfl_up_sync(0xffffffffu, incs, o);
        if (lane >= o) incs += t;
    }
    int* wsum = hist;
    if (lane == 31) wsum[wid] = incs;
    __syncthreads();
    if (wid == 0) {
        int ws = wsum[lane], wi = ws;
        #pragma unroll
        for (int o = 1; o < 32; o <<= 1) {
            int t = __shfl_up_sync(0xffffffffu, wi, o);
            if (lane >= o) wi += t;
        }
        wsum[lane] = wi - ws;
    }
    __syncthreads();
    int before = wsum[wid] + incs - pk;
    int sk_before  = before & 0xFFFF;
    int tie_before = before >> 16;
    int acc_f = strict | (tie & (tie_before < R ? 1 : 0));
    int newid = sk_before + (tie_before < R ? tie_before : R);
    s_map[tid] = acc_f ? newid : -1;
    if (acc_f) s_perm[newid] = tid;
    __syncthreads();

    if (tid < ncur && b < 3) g_mapG[g * ncur + tid] = s_map[tid];
    if (tid < ksel) g_permG[g * ksel + tid] = s_perm[tid];
}

// ---------------- postsel: gatherread (y < ngchunks) + compact (y >= ngchunks), one launch ----------------
__global__ __launch_bounds__(256)
void postsel_kernel(int b, int ncur, int ksel, int sel, int ngchunks) {
    int g = blockIdx.x;
    int y = blockIdx.y;
    int tid = threadIdx.x, wid = tid >> 5, lane = tid & 31;

    if (y < ngchunks) {
        // ======== gatherread: gather + tanh gate + readout partials ========
        __shared__ float ssum[8][128];
        __shared__ unsigned int smax[8][128];
        int row0 = y * 32;
        int c = lane * 4;
        float4 rsum = make_float4(0.f, 0.f, 0.f, 0.f);
        float4 rmax = make_float4(-FLT_MAX, -FLT_MAX, -FLT_MAX, -FLT_MAX);
        #pragma unroll
        for (int r = 0; r < 4; r++) {
            int nw = row0 + wid * 4 + r;
            if (nw < ksel) {
                int old = g_permG[g * ksel + nw];
                float t = tanhf(g_score[g * ncur + old]);
                float4 h = *((const float4*)(g_bufB + (size_t)(g * ncur + old) * H_) + lane);
                h.x *= t; h.y *= t; h.z *= t; h.w *= t;
                if (b < 3) *((float4*)(g_bufA + (size_t)(g * ksel + nw) * H_) + lane) = h;
                rsum.x += h.x; rsum.y += h.y; rsum.z += h.z; rsum.w += h.w;
                rmax.x = fmaxf(rmax.x, h.x); rmax.y = fmaxf(rmax.y, h.y);
                rmax.z = fmaxf(rmax.z, h.z); rmax.w = fmaxf(rmax.w, h.w);
            }
        }
        *(float4*)&ssum[wid][c] = rsum;
        {
            unsigned int ux = __float_as_uint(rmax.x);
            unsigned int uy = __float_as_uint(rmax.y);
            unsigned int uz = __float_as_uint(rmax.z);
            unsigned int uw = __float_as_uint(rmax.w);
            smax[wid][c + 0] = (ux & 0x80000000u) ? ~ux : (ux | 0x80000000u);
            smax[wid][c + 1] = (uy & 0x80000000u) ? ~uy : (uy | 0x80000000u);
            smax[wid][c + 2] = (uz & 0x80000000u) ? ~uz : (uz | 0x80000000u);
            smax[wid][c + 3] = (uw & 0x80000000u) ? ~uw : (uw | 0x80000000u);
        }
        __syncthreads();
        if (tid < 128) {
            float s = 0.f;
            unsigned int m = 0u;
            #pragma unroll
            for (int w = 0; w < 8; w++) {
                s += ssum[w][tid];
                m = max(m, smax[w][tid]);
            }
            atomicAdd(&g_flat[g * 1024 + b * 256 + tid], s);
            atomicMax(&g_fmax[(g * 4 + b) * 128 + tid], m);
        }
    } else {
        // ======== compact: old pooled CSR -> new pooled CSR (warp per new node) ========
        const int* ocnt = sel ? g_cnt1 : g_cnt0;
        const int* ooff = sel ? g_off1 : g_off0;
        const int* ocsr = sel ? g_csrB : g_csrA;
        int* ncnt = sel ? g_cnt0 : g_cnt1;
        int* noff = sel ? g_off0 : g_off1;
        int* ncsr = sel ? g_csrA : g_csrB;

        int nl = (y - ngchunks) * 8 + wid;       // local new node id
        if (nl >= ksel) return;
        int n = g * ksel + nl;
        int og = g * ncur + g_permG[n];
        int deg  = ocnt[og];
        int base = ooff[og];
        int gk = g * ksel;
        int cum = 0;
        for (int j0 = 0; j0 < deg; j0 += 32) {
            int j = j0 + lane;
            int m = -1;
            if (j < deg) m = g_mapG[ocsr[base + j]];
            unsigned int mk = __ballot_sync(0xffffffffu, m >= 0);
            if (m >= 0) {
                int pos = __popc(mk & ((1u << lane) - 1u));
                ncsr[base + cum + pos] = gk + m;
            }
            cum += __popc(mk);
        }
        if (lane == 0) { ncnt[n] = cum; noff[n] = base; }
    }
}

// ---------------- MLP head ----------------
__global__ __launch_bounds__(512)
void head_kernel(const float* __restrict__ Wd1, const float* __restrict__ bd1,
                 const float* __restrict__ Wd2, const float* __restrict__ bd2,
                 float* __restrict__ out) {
    __shared__ float a[1024];
    __shared__ float hd[512];
    int g = blockIdx.x, tid = threadIdx.x;
    for (int j = tid; j < 1024; j += 512) {
        int bb = j >> 8, r = j & 255;
        float v;
        if (r < 128) {
            v = g_flat[g * 1024 + bb * 256 + r];
        } else {
            unsigned int u = g_fmax[(g * 4 + bb) * 128 + (r - 128)];
            v = (u & 0x80000000u) ? __uint_as_float(u ^ 0x80000000u)
                                  : __uint_as_float(~u);
        }
        a[j] = v;
    }
    __syncthreads();
    {
        float a0 = 0.f, a1 = 0.f, a2 = 0.f, a3 = 0.f;
        #pragma unroll 4
        for (int kk = 0; kk < 1024; kk += 4) {
            a0 += a[kk + 0] * Wd1[(kk + 0) * 512 + tid];
            a1 += a[kk + 1] * Wd1[(kk + 1) * 512 + tid];
            a2 += a[kk + 2] * Wd1[(kk + 2) * 512 + tid];
            a3 += a[kk + 3] * Wd1[(kk + 3) * 512 + tid];
        }
        hd[tid] = fmaxf(a0 + a1 + a2 + a3 + bd1[tid], 0.f);
    }
    __syncthreads();
    if (tid < 320) {
        int cc = tid >> 5, l = tid & 31;
        float acc = 0.f;
        for (int kk = l; kk < 512; kk += 32) acc += hd[kk] * Wd2[kk * 10 + cc];
        #pragma unroll
        for (int o = 16; o > 0; o >>= 1) acc += __shfl_down_sync(0xffffffffu, acc, o);
        if (l == 0) out[g * 10 + cc] = acc + bd2[cc];
    }
}

// ---------------- launcher ----------------
extern "C" void kernel_launch(void* const* d_in, const int* in_sizes, int n_in,
                              void* d_out, int out_size) {
    const float* x  = (const float*)d_in[0];
    const int*   ei = (const int*)d_in[1];
    const float *Wl[4], *Wr[4], *bb[4], *gw[4], *be[4], *pp[4];
    int idx = 3;
    for (int b = 0; b < 4; b++) {
        Wl[b] = (const float*)d_in[idx++];
        Wr[b] = (const float*)d_in[idx++];
        bb[b] = (const float*)d_in[idx++];
        gw[b] = (const float*)d_in[idx++];
        be[b] = (const float*)d_in[idx++];
        pp[b] = (const float*)d_in[idx++];
    }
    const float* Wd1 = (const float*)d_in[27];
    const float* bd1 = (const float*)d_in[28];
    const float* Wd2 = (const float*)d_in[29];
    const float* bd2 = (const float*)d_in[30];
    float* out = (float*)d_out;

    cudaFuncSetAttribute(gemm_kernel, cudaFuncAttributeMaxDynamicSharedMemorySize,
                         SMEM_GEMM_BYTES);
    cudaFuncSetAttribute(mega_kernel, cudaFuncAttributeMaxDynamicSharedMemorySize,
                         MEGA_SMEM);

    csr0_kernel<<<G_, 1024>>>(ei);

    for (int b = 0; b < 4; b++) {
        int ncur = NCUR_H[b];
        int k    = KSEL_H[b];
        int nt   = G_ * ncur;
        int first = (b == 0) ? 1 : 0;
        int sel   = b & 1;
        float invnt = 1.0f / (float)nt;

        gemm_kernel<<<(nt + 63) / 64, 256, SMEM_GEMM_BYTES>>>(
            x, first, b, sel, Wl[b], Wr[b], bb[b], nt);
        bnscore_kernel<<<(nt + 7) / 8, 256>>>(gw[b], be[b], pp[b], nt, invnt, b);
        mega_kernel<<<G_, 1024, MEGA_SMEM>>>(b, ncur, k);

        int ngchunks = (k + 31) / 32;
        int ncchunks = (b < 3) ? (k + 7) / 8 : 0;
        postsel_kernel<<<dim3(G_, ngchunks + ncchunks), 256>>>(b, ncur, k, sel, ngchunks);
    }
    head_kernel<<<G_, 512>>>(Wd1, bd1, Wd2, bd2, out);
}